// round 10
// baseline (speedup 1.0000x reference)
#include <cuda_runtime.h>
#include <cuda_fp16.h>
#include <math.h>
#include <stdint.h>

#define B_ 4
#define T_ 2048
#define C_ 2048
#define H_ 16
#define D_ 128
#define L_ 512
#define BT_ (B_*T_)
#define NQL 2560
#define NKV 256

// ---------------- scratch ----------------
__device__ __half g_xhi[(size_t)BT_ * C_];      // x splits -> (after q GEMM) y splits
__device__ __half g_xlo[(size_t)BT_ * C_];
__device__ __half g_qh[(size_t)BT_ * C_];       // rope(q) hi/lo
__device__ __half g_ql[(size_t)BT_ * C_];
__device__ __half g_lhi[(size_t)BT_ * L_];
__device__ __half g_llo[(size_t)BT_ * L_];
__device__ __half g_kh[(size_t)BT_ * D_];
__device__ __half g_vh[(size_t)BT_ * D_];
__device__ __half g_wqkvh[(size_t)NQL * C_];
__device__ __half g_wuph[(size_t)NKV * L_];
__device__ __half g_woh[(size_t)C_ * H_ * D_];

// ---------------- helpers ----------------
__device__ __forceinline__ uint32_t smem_u32(const void* p) {
    uint32_t a;
    asm("{ .reg .u64 t; cvta.to.shared.u64 t, %1; cvt.u32.u64 %0, t; }"
        : "=r"(a) : "l"(p));
    return a;
}
__device__ __forceinline__ void cp_async16(uint32_t dst, const void* src) {
    asm volatile("cp.async.cg.shared.global [%0], [%1], 16;"
                 :: "r"(dst), "l"(src) : "memory");
}
#define CP_COMMIT() asm volatile("cp.async.commit_group;" ::: "memory")
#define CP_WAIT2()  asm volatile("cp.async.wait_group 2;" ::: "memory")
#define CP_WAIT1()  asm volatile("cp.async.wait_group 1;" ::: "memory")
#define CP_WAIT0()  asm volatile("cp.async.wait_group 0;" ::: "memory")

__device__ __forceinline__ void ldm_x4(uint32_t& r0, uint32_t& r1,
                                       uint32_t& r2, uint32_t& r3, uint32_t a) {
    asm volatile("ldmatrix.sync.aligned.m8n8.x4.shared.b16 {%0,%1,%2,%3}, [%4];"
                 : "=r"(r0), "=r"(r1), "=r"(r2), "=r"(r3) : "r"(a));
}
__device__ __forceinline__ void ldm_x4_t(uint32_t& r0, uint32_t& r1,
                                         uint32_t& r2, uint32_t& r3, uint32_t a) {
    asm volatile("ldmatrix.sync.aligned.m8n8.x4.trans.shared.b16 {%0,%1,%2,%3}, [%4];"
                 : "=r"(r0), "=r"(r1), "=r"(r2), "=r"(r3) : "r"(a));
}
__device__ __forceinline__ void mma16816(float* d, const uint32_t* a,
                                         uint32_t b0, uint32_t b1) {
    asm volatile(
        "mma.sync.aligned.m16n8k16.row.col.f32.f16.f16.f32 "
        "{%0,%1,%2,%3}, {%4,%5,%6,%7}, {%8,%9}, {%0,%1,%2,%3};"
        : "+f"(d[0]), "+f"(d[1]), "+f"(d[2]), "+f"(d[3])
        : "r"(a[0]), "r"(a[1]), "r"(a[2]), "r"(a[3]), "r"(b0), "r"(b1));
}
__device__ __forceinline__ uint32_t pack_h2(float lo, float hi) {
    uint32_t r;
    asm("cvt.rn.f16x2.f32 %0, %1, %2;" : "=r"(r) : "f"(hi), "f"(lo));
    return r;
}

// ---------------- conversion kernels ----------------
__global__ void cvt_split_h(const float* __restrict__ s,
                            __half* __restrict__ hi, __half* __restrict__ lo, int n4)
{
    int i = blockIdx.x * blockDim.x + threadIdx.x;
    if (i >= n4) return;
    float4 v = *(const float4*)(s + (size_t)i * 4);
    __half h0 = __float2half_rn(v.x), h1 = __float2half_rn(v.y);
    __half h2 = __float2half_rn(v.z), h3 = __float2half_rn(v.w);
    *(__half2*)(hi + (size_t)i * 4)     = __halves2half2(h0, h1);
    *(__half2*)(hi + (size_t)i * 4 + 2) = __halves2half2(h2, h3);
    *(__half2*)(lo + (size_t)i * 4)     = __halves2half2(
        __float2half_rn(v.x - __half2float(h0)), __float2half_rn(v.y - __half2float(h1)));
    *(__half2*)(lo + (size_t)i * 4 + 2) = __halves2half2(
        __float2half_rn(v.z - __half2float(h2)), __float2half_rn(v.w - __half2float(h3)));
}
__global__ void cvt_h(const float* __restrict__ s, __half* __restrict__ d, int n4)
{
    int i = blockIdx.x * blockDim.x + threadIdx.x;
    if (i >= n4) return;
    float4 v = *(const float4*)(s + (size_t)i * 4);
    *(__half2*)(d + (size_t)i * 4)     = __halves2half2(__float2half_rn(v.x), __float2half_rn(v.y));
    *(__half2*)(d + (size_t)i * 4 + 2) = __halves2half2(__float2half_rn(v.z), __float2half_rn(v.w));
}

// ---------------- single-pass dual-A mma.sync GEMM with fused epilogues ----------------
// C = (Ahi+Alo) * Bh^T.  mode 0: fp32 out.
// mode 1 (q+lat): col<2048 -> rope -> (O1h,O1l); col>=2048 -> split -> (O2h,O2l)
// mode 2 (k+v):   col<128  -> rope -> O1h;      col>=128  -> O2h
#define GBK 32
#define GSTG 4
#define GTB 8192
#define GM_SMEM (3 * GSTG * GTB)      // 98304

__global__ __launch_bounds__(256, 2) void gemm_f16d(
    const __half* __restrict__ Ahi, const __half* __restrict__ Alo,
    const __half* __restrict__ Bh, float* __restrict__ Cf,
    __half* __restrict__ O1h, __half* __restrict__ O1l,
    __half* __restrict__ O2h, __half* __restrict__ O2l,
    const float* __restrict__ cs, const float* __restrict__ sn,
    int N, int K, int mode)
{
    extern __shared__ char smraw[];
    const uint32_t sAh = smem_u32(smraw);
    const uint32_t sAl = sAh + GSTG * GTB;
    const uint32_t sB  = sAh + 2 * GSTG * GTB;

    const int tid  = threadIdx.x;
    const int wid  = tid >> 5;
    const int lane = tid & 31;
    const int wm = wid >> 2;
    const int wn = wid & 3;
    const int n0 = blockIdx.x * 128;
    const int m0 = blockIdx.y * 128;
    const int KB = K / GBK;

    float acc[4][4][4];
#pragma unroll
    for (int i = 0; i < 4; i++)
#pragma unroll
        for (int j = 0; j < 4; j++)
#pragma unroll
            for (int u = 0; u < 4; u++) acc[i][j][u] = 0.f;

    auto load_stage = [&](int kc, int s) {
        const uint32_t ah = sAh + (uint32_t)s * GTB;
        const uint32_t al = sAl + (uint32_t)s * GTB;
        const uint32_t bs = sB  + (uint32_t)s * GTB;
#pragma unroll
        for (int i = 0; i < 2; i++) {
            int ch  = tid + i * 256;
            int row = ch >> 2;
            int c   = ch & 3;
            int csw = c ^ ((row >> 1) & 3);
            uint32_t off = (uint32_t)(row * 64 + csw * 16);
            const size_t ga = (size_t)(m0 + row) * K + kc * GBK + c * 8;
            cp_async16(ah + off, Ahi + ga);
            cp_async16(al + off, Alo + ga);
            cp_async16(bs + off, Bh + (size_t)(n0 + row) * K + kc * GBK + c * 8);
        }
    };

    load_stage(0, 0); CP_COMMIT();
    load_stage(1, 1); CP_COMMIT();
    load_stage(2, 2); CP_COMMIT();

    for (int kc = 0; kc < KB; kc++) {
        const int s = kc & 3;
        CP_WAIT2();
        __syncthreads();
        if (kc + 3 < KB) load_stage(kc + 3, (kc + 3) & 3);
        CP_COMMIT();

        const uint32_t ah = sAh + (uint32_t)s * GTB;
        const uint32_t al = sAl + (uint32_t)s * GTB;
        const uint32_t bs = sB  + (uint32_t)s * GTB;
#pragma unroll
        for (int kk = 0; kk < 2; kk++) {
            uint32_t a[4][4], b[2][4];
#pragma unroll
            for (int np = 0; np < 2; np++) {
                int row = wn * 32 + np * 16 + (lane & 15);
                int cc  = kk * 2 + (lane >> 4);
                int csw = cc ^ ((row >> 1) & 3);
                ldm_x4(b[np][0], b[np][1], b[np][2], b[np][3],
                       bs + (uint32_t)(row * 64 + csw * 16));
            }
#pragma unroll
            for (int mt = 0; mt < 4; mt++) {
                int row = wm * 64 + mt * 16 + (lane & 15);
                int cc  = kk * 2 + (lane >> 4);
                int csw = cc ^ ((row >> 1) & 3);
                ldm_x4(a[mt][0], a[mt][1], a[mt][2], a[mt][3],
                       ah + (uint32_t)(row * 64 + csw * 16));
            }
#pragma unroll
            for (int mt = 0; mt < 4; mt++)
#pragma unroll
                for (int nt = 0; nt < 4; nt++)
                    mma16816(acc[mt][nt], a[mt],
                             b[nt >> 1][nt & 1], b[nt >> 1][(nt & 1) + 2]);
#pragma unroll
            for (int mt = 0; mt < 4; mt++) {
                int row = wm * 64 + mt * 16 + (lane & 15);
                int cc  = kk * 2 + (lane >> 4);
                int csw = cc ^ ((row >> 1) & 3);
                ldm_x4(a[mt][0], a[mt][1], a[mt][2], a[mt][3],
                       al + (uint32_t)(row * 64 + csw * 16));
            }
#pragma unroll
            for (int mt = 0; mt < 4; mt++)
#pragma unroll
                for (int nt = 0; nt < 4; nt++)
                    mma16816(acc[mt][nt], a[mt],
                             b[nt >> 1][nt & 1], b[nt >> 1][(nt & 1) + 2]);
        }
        __syncthreads();
    }

    // ---- epilogue ----
    const int r0g = m0 + wm * 64 + (lane >> 2);
    const int c0g = n0 + wn * 32 + (lane & 3) * 2;
#pragma unroll
    for (int mt = 0; mt < 4; mt++)
#pragma unroll
        for (int nt = 0; nt < 4; nt++)
#pragma unroll
            for (int u = 0; u < 2; u++) {
                const int rg = r0g + mt * 16 + u * 8;
                const int cg = c0g + nt * 8;
                float v0 = acc[mt][nt][u * 2];
                float v1 = acc[mt][nt][u * 2 + 1];
                if (mode == 0) {
                    *(float2*)(Cf + (size_t)rg * N + cg) = make_float2(v0, v1);
                } else if (mode == 1) {
                    const int t = rg & (T_ - 1);
                    if (cg < C_) {
                        int jj = (cg & 127) >> 1;
                        float c = cs[t * 64 + jj], s = sn[t * 64 + jj];
                        float o0 = v0 * c - v1 * s;
                        float o1 = v0 * s + v1 * c;
                        __half h0 = __float2half_rn(o0), h1 = __float2half_rn(o1);
                        size_t o = (size_t)rg * C_ + cg;
                        *(__half2*)(O1h + o) = __halves2half2(h0, h1);
                        *(__half2*)(O1l + o) = __halves2half2(
                            __float2half_rn(o0 - __half2float(h0)),
                            __float2half_rn(o1 - __half2float(h1)));
                    } else {
                        __half h0 = __float2half_rn(v0), h1 = __float2half_rn(v1);
                        size_t o = (size_t)rg * L_ + (cg - C_);
                        *(__half2*)(O2h + o) = __halves2half2(h0, h1);
                        *(__half2*)(O2l + o) = __halves2half2(
                            __float2half_rn(v0 - __half2float(h0)),
                            __float2half_rn(v1 - __half2float(h1)));
                    }
                } else {
                    const int t = rg & (T_ - 1);
                    if (cg < D_) {
                        int jj = cg >> 1;
                        float c = cs[t * 64 + jj], s = sn[t * 64 + jj];
                        float o0 = v0 * c - v1 * s;
                        float o1 = v0 * s + v1 * c;
                        *(__half2*)(O1h + (size_t)rg * D_ + cg) =
                            __halves2half2(__float2half_rn(o0), __float2half_rn(o1));
                    } else {
                        *(__half2*)(O2h + (size_t)rg * D_ + (cg - D_)) =
                            __halves2half2(__float2half_rn(v0), __float2half_rn(v1));
                    }
                }
            }
}

// ---------------- mma.sync flash attention (fp16, 2-pass QK, 2-pass PV) ----------------
#define AST 136
#define QT_B (128 * AST * 2)
#define KT_B (64 * AST * 2)
#define STG_B (2 * KT_B)
#define ATT_SMEM (2 * QT_B + 2 * STG_B)

__global__ __launch_bounds__(256, 1) void attn_mma(
    const __half* __restrict__ qhi, const __half* __restrict__ qlo,
    const __half* __restrict__ kh, const __half* __restrict__ vh,
    __half* __restrict__ yhi, __half* __restrict__ ylo)
{
    extern __shared__ char smraw[];
    const uint32_t sQhi = smem_u32(smraw);
    const uint32_t sQlo = sQhi + QT_B;
    const uint32_t sStg = sQlo + QT_B;

    const int tid  = threadIdx.x;
    const int wid  = tid >> 5;
    const int lane = tid & 31;
    const int qt = (T_ / 128 - 1) - blockIdx.x;
    const int h  = blockIdx.y, b = blockIdx.z;
    const int t0 = qt * 128;
    const int jmax = 2 * qt + 1;
    const float scale = 0.08838834764831845f;

    {
        const size_t qb = (((size_t)b * T_ + t0) * H_ + h) * D_;
#pragma unroll
        for (int i = 0; i < 8; i++) {
            int ch  = tid + i * 256;
            int row = ch >> 4;
            int c16 = ch & 15;
            uint32_t doff = (uint32_t)(row * AST + c16 * 8) * 2;
            size_t   soff = qb + (size_t)row * (H_ * D_) + c16 * 8;
            cp_async16(sQhi + doff, qhi + soff);
            cp_async16(sQlo + doff, qlo + soff);
        }
    }
    auto load_stage = [&](int j, int s) {
        const uint32_t sb = sStg + (uint32_t)s * STG_B;
        const size_t   gb = ((size_t)b * T_ + j * 64) * D_;
#pragma unroll
        for (int i = 0; i < 4; i++) {
            int ch  = tid + i * 256;
            int row = ch >> 4;
            int c16 = ch & 15;
            uint32_t doff = (uint32_t)(row * AST + c16 * 8) * 2;
            size_t   soff = gb + (size_t)row * D_ + c16 * 8;
            cp_async16(sb + doff,        kh + soff);
            cp_async16(sb + KT_B + doff, vh + soff);
        }
    };
    load_stage(0, 0); CP_COMMIT();
    load_stage(1, 1); CP_COMMIT();

    float m0 = -3.0e38f, m1 = -3.0e38f, l0 = 0.f, l1 = 0.f;
    float yacc[16][4];
#pragma unroll
    for (int nt = 0; nt < 16; nt++)
#pragma unroll
        for (int u = 0; u < 4; u++) yacc[nt][u] = 0.f;

    const int rloc = wid * 16 + (lane >> 2);

    for (int j = 0; j <= jmax; j++) {
        const int s = j & 1;
        if (j < jmax) { CP_WAIT1(); } else { CP_WAIT0(); }
        __syncthreads();
        const uint32_t sKh = sStg + (uint32_t)s * STG_B;
        const uint32_t sVh = sKh + KT_B;

        float sacc[8][4];
#pragma unroll
        for (int nt = 0; nt < 8; nt++)
#pragma unroll
            for (int u = 0; u < 4; u++) sacc[nt][u] = 0.f;

#pragma unroll
        for (int kk = 0; kk < 8; kk++) {
            uint32_t ah[4], al[4], bb[4][4];
            {
                int row = wid * 16 + (lane & 15);
                int col = kk * 16 + (lane >> 4) * 8;
                uint32_t off = (uint32_t)(row * AST + col) * 2;
                ldm_x4(ah[0], ah[1], ah[2], ah[3], sQhi + off);
                ldm_x4(al[0], al[1], al[2], al[3], sQlo + off);
            }
#pragma unroll
            for (int nt2 = 0; nt2 < 4; nt2++) {
                int row = nt2 * 16 + (lane & 15);
                int col = kk * 16 + (lane >> 4) * 8;
                ldm_x4(bb[nt2][0], bb[nt2][1], bb[nt2][2], bb[nt2][3],
                       sKh + (uint32_t)(row * AST + col) * 2);
            }
#pragma unroll
            for (int nt = 0; nt < 8; nt++) {
                mma16816(sacc[nt], ah, bb[nt >> 1][nt & 1], bb[nt >> 1][(nt & 1) + 2]);
                mma16816(sacc[nt], al, bb[nt >> 1][nt & 1], bb[nt >> 1][(nt & 1) + 2]);
            }
        }

        const bool need_mask = (j >= jmax - 1);
#pragma unroll
        for (int nt = 0; nt < 8; nt++)
#pragma unroll
            for (int u = 0; u < 4; u++) {
                float v = sacc[nt][u] * scale;
                if (need_mask) {
                    int rg = t0 + rloc + (u >> 1) * 8;
                    int cg = j * 64 + nt * 8 + (lane & 3) * 2 + (u & 1);
                    if (cg > rg) v = -1.0e30f;
                }
                sacc[nt][u] = v;
            }

        float rx0 = -3.0e38f, rx1 = -3.0e38f;
#pragma unroll
        for (int nt = 0; nt < 8; nt++) {
            rx0 = fmaxf(rx0, fmaxf(sacc[nt][0], sacc[nt][1]));
            rx1 = fmaxf(rx1, fmaxf(sacc[nt][2], sacc[nt][3]));
        }
        rx0 = fmaxf(rx0, __shfl_xor_sync(0xffffffffu, rx0, 1));
        rx0 = fmaxf(rx0, __shfl_xor_sync(0xffffffffu, rx0, 2));
        rx1 = fmaxf(rx1, __shfl_xor_sync(0xffffffffu, rx1, 1));
        rx1 = fmaxf(rx1, __shfl_xor_sync(0xffffffffu, rx1, 2));
        float mn0 = fmaxf(m0, rx0), mn1 = fmaxf(m1, rx1);
        float sc0 = __expf(m0 - mn0), sc1 = __expf(m1 - mn1);
        m0 = mn0; m1 = mn1;

        float rs0 = 0.f, rs1 = 0.f;
#pragma unroll
        for (int nt = 0; nt < 8; nt++) {
            sacc[nt][0] = __expf(sacc[nt][0] - mn0);
            sacc[nt][1] = __expf(sacc[nt][1] - mn0);
            sacc[nt][2] = __expf(sacc[nt][2] - mn1);
            sacc[nt][3] = __expf(sacc[nt][3] - mn1);
            rs0 += sacc[nt][0] + sacc[nt][1];
            rs1 += sacc[nt][2] + sacc[nt][3];
        }
        rs0 += __shfl_xor_sync(0xffffffffu, rs0, 1);
        rs0 += __shfl_xor_sync(0xffffffffu, rs0, 2);
        rs1 += __shfl_xor_sync(0xffffffffu, rs1, 1);
        rs1 += __shfl_xor_sync(0xffffffffu, rs1, 2);
        l0 = l0 * sc0 + rs0;
        l1 = l1 * sc1 + rs1;

#pragma unroll
        for (int nt = 0; nt < 16; nt++) {
            yacc[nt][0] *= sc0; yacc[nt][1] *= sc0;
            yacc[nt][2] *= sc1; yacc[nt][3] *= sc1;
        }

        uint32_t phiA[4][4], ploA[4][4];
#pragma unroll
        for (int kk2 = 0; kk2 < 4; kk2++) {
            const int ta = 2 * kk2, tb2 = 2 * kk2 + 1;
            float ph[8], pl[8];
            const float* src[2] = { sacc[ta], sacc[tb2] };
#pragma unroll
            for (int q2 = 0; q2 < 2; q2++)
#pragma unroll
                for (int u = 0; u < 4; u++) {
                    float p = src[q2][u];
                    __half hh = __float2half_rn(p);
                    ph[q2 * 4 + u] = __half2float(hh);
                    pl[q2 * 4 + u] = p - ph[q2 * 4 + u];
                }
            phiA[kk2][0] = pack_h2(ph[0], ph[1]);
            phiA[kk2][1] = pack_h2(ph[2], ph[3]);
            phiA[kk2][2] = pack_h2(ph[4], ph[5]);
            phiA[kk2][3] = pack_h2(ph[6], ph[7]);
            ploA[kk2][0] = pack_h2(pl[0], pl[1]);
            ploA[kk2][1] = pack_h2(pl[2], pl[3]);
            ploA[kk2][2] = pack_h2(pl[4], pl[5]);
            ploA[kk2][3] = pack_h2(pl[6], pl[7]);
        }

#pragma unroll
        for (int kk2 = 0; kk2 < 4; kk2++) {
            uint32_t vb[8][4];
#pragma unroll
            for (int nt2 = 0; nt2 < 8; nt2++) {
                int row = kk2 * 16 + (lane & 15);
                int col = nt2 * 16 + (lane >> 4) * 8;
                ldm_x4_t(vb[nt2][0], vb[nt2][1], vb[nt2][2], vb[nt2][3],
                         sVh + (uint32_t)(row * AST + col) * 2);
            }
#pragma unroll
            for (int nt = 0; nt < 16; nt++) {
                mma16816(yacc[nt], phiA[kk2],
                         vb[nt >> 1][(nt & 1) * 2], vb[nt >> 1][(nt & 1) * 2 + 1]);
                mma16816(yacc[nt], ploA[kk2],
                         vb[nt >> 1][(nt & 1) * 2], vb[nt >> 1][(nt & 1) * 2 + 1]);
            }
        }

        __syncthreads();
        if (j + 2 <= jmax) { load_stage(j + 2, s); CP_COMMIT(); }
    }

    const float inv0 = 1.f / l0, inv1 = 1.f / l1;
#pragma unroll
    for (int half = 0; half < 2; half++) {
        const int rg = t0 + rloc + half * 8;
        const float inv = half ? inv1 : inv0;
        __half* ph = yhi + (((size_t)b * T_ + rg) * H_ + h) * D_;
        __half* pl = ylo + (((size_t)b * T_ + rg) * H_ + h) * D_;
#pragma unroll
        for (int nt = 0; nt < 16; nt++) {
            int cg = nt * 8 + (lane & 3) * 2;
            float v0 = yacc[nt][half * 2]     * inv;
            float v1 = yacc[nt][half * 2 + 1] * inv;
            __half h0 = __float2half_rn(v0), h1 = __float2half_rn(v1);
            *(__half2*)(ph + cg) = __halves2half2(h0, h1);
            *(__half2*)(pl + cg) = __halves2half2(
                __float2half_rn(v0 - __half2float(h0)),
                __float2half_rn(v1 - __half2float(h1)));
        }
    }
}

// ---------------- host launcher ----------------
extern "C" void kernel_launch(void* const* d_in, const int* in_sizes, int n_in,
                              void* d_out, int out_size)
{
    const float* x     = (const float*)d_in[0];
    const float* fcos  = (const float*)d_in[1];
    const float* fsin  = (const float*)d_in[2];
    const float* wq    = (const float*)d_in[3];
    const float* wkv   = (const float*)d_in[4];
    const float* wk_up = (const float*)d_in[5];
    const float* wv_up = (const float*)d_in[6];
    const float* wo    = (const float*)d_in[7];
    float* out = (float*)d_out;

    __half *xhi, *xlo, *qh, *ql, *lhi, *llo, *kh, *vh, *wqkvh, *wuph, *woh;
    cudaGetSymbolAddress((void**)&xhi,   g_xhi);
    cudaGetSymbolAddress((void**)&xlo,   g_xlo);
    cudaGetSymbolAddress((void**)&qh,    g_qh);
    cudaGetSymbolAddress((void**)&ql,    g_ql);
    cudaGetSymbolAddress((void**)&lhi,   g_lhi);
    cudaGetSymbolAddress((void**)&llo,   g_llo);
    cudaGetSymbolAddress((void**)&kh,    g_kh);
    cudaGetSymbolAddress((void**)&vh,    g_vh);
    cudaGetSymbolAddress((void**)&wqkvh, g_wqkvh);
    cudaGetSymbolAddress((void**)&wuph,  g_wuph);
    cudaGetSymbolAddress((void**)&woh,   g_woh);

    cudaFuncSetAttribute(gemm_f16d,
                         cudaFuncAttributeMaxDynamicSharedMemorySize, GM_SMEM);
    cudaFuncSetAttribute(attn_mma,
                         cudaFuncAttributeMaxDynamicSharedMemorySize, ATT_SMEM);

    // conversions
    cvt_split_h<<<(BT_*C_/4)/256, 256>>>(x, xhi, xlo, BT_*C_/4);
    cvt_h<<<(H_*D_*C_/4)/256, 256>>>(wq, wqkvh, H_*D_*C_/4);
    cvt_h<<<(L_*C_/4)/256, 256>>>(wkv, wqkvh + (size_t)H_*D_*C_, L_*C_/4);
    cvt_h<<<(D_*L_/4)/256, 256>>>(wk_up, wuph, D_*L_/4);
    cvt_h<<<(D_*L_/4)/256, 256>>>(wv_up, wuph + (size_t)D_*L_, D_*L_/4);
    cvt_h<<<(C_*H_*D_/4)/256, 256>>>(wo, woh, C_*H_*D_/4);

    // q+lat projection, fused rope+split epilogue
    gemm_f16d<<<dim3(NQL/128, BT_/128), 256, GM_SMEM>>>(
        xhi, xlo, wqkvh, nullptr, qh, ql, lhi, llo, fcos, fsin, NQL, C_, 1);
    // k+v up-projection, fused rope/cvt epilogue
    gemm_f16d<<<dim3(NKV/128, BT_/128), 256, GM_SMEM>>>(
        lhi, llo, wuph, nullptr, kh, nullptr, vh, nullptr, fcos, fsin, NKV, L_, 2);

    // attention: y splits overwrite x splits (dead after q+lat GEMM)
    attn_mma<<<dim3(T_/128, H_, B_), 256, ATT_SMEM>>>(
        qh, ql, kh, vh, xhi, xlo);

    // output projection, fp32 epilogue
    gemm_f16d<<<dim3(C_/128, BT_/128), 256, GM_SMEM>>>(
        xhi, xlo, woh, out, nullptr, nullptr, nullptr, nullptr,
        nullptr, nullptr, C_, H_*D_, 0);
}

// round 11
// speedup vs baseline: 1.6660x; 1.6660x over previous
#include <cuda_runtime.h>
#include <cuda_fp16.h>
#include <math.h>
#include <stdint.h>

#define B_ 4
#define T_ 2048
#define C_ 2048
#define H_ 16
#define D_ 128
#define L_ 512
#define BT_ (B_*T_)
#define NQL 2560
#define NKV 256

// ---------------- scratch ----------------
__device__ __half g_xhi[(size_t)BT_ * C_];      // x splits -> (after attn) y splits
__device__ __half g_xlo[(size_t)BT_ * C_];
__device__ __half g_qh[(size_t)BT_ * C_];       // rope(q) hi/lo
__device__ __half g_ql[(size_t)BT_ * C_];
__device__ __half g_lhi[(size_t)BT_ * L_];
__device__ __half g_llo[(size_t)BT_ * L_];
__device__ __half g_kh[(size_t)BT_ * D_];
__device__ __half g_vh[(size_t)BT_ * D_];
__device__ __half g_wqkvh[(size_t)NQL * C_];
__device__ __half g_wuph[(size_t)NKV * L_];
__device__ __half g_woh[(size_t)C_ * H_ * D_];

// ---------------- helpers ----------------
__device__ __forceinline__ uint32_t smem_u32(const void* p) {
    uint32_t a;
    asm("{ .reg .u64 t; cvta.to.shared.u64 t, %1; cvt.u32.u64 %0, t; }"
        : "=r"(a) : "l"(p));
    return a;
}
__device__ __forceinline__ void cp_async16(uint32_t dst, const void* src) {
    asm volatile("cp.async.cg.shared.global [%0], [%1], 16;"
                 :: "r"(dst), "l"(src) : "memory");
}
#define CP_COMMIT() asm volatile("cp.async.commit_group;" ::: "memory")
#define CP_WAIT1()  asm volatile("cp.async.wait_group 1;" ::: "memory")
#define CP_WAIT0()  asm volatile("cp.async.wait_group 0;" ::: "memory")

__device__ __forceinline__ void ldm_x4(uint32_t& r0, uint32_t& r1,
                                       uint32_t& r2, uint32_t& r3, uint32_t a) {
    asm volatile("ldmatrix.sync.aligned.m8n8.x4.shared.b16 {%0,%1,%2,%3}, [%4];"
                 : "=r"(r0), "=r"(r1), "=r"(r2), "=r"(r3) : "r"(a));
}
__device__ __forceinline__ void ldm_x4_t(uint32_t& r0, uint32_t& r1,
                                         uint32_t& r2, uint32_t& r3, uint32_t a) {
    asm volatile("ldmatrix.sync.aligned.m8n8.x4.trans.shared.b16 {%0,%1,%2,%3}, [%4];"
                 : "=r"(r0), "=r"(r1), "=r"(r2), "=r"(r3) : "r"(a));
}
__device__ __forceinline__ void mma16816(float* d, const uint32_t* a,
                                         uint32_t b0, uint32_t b1) {
    asm volatile(
        "mma.sync.aligned.m16n8k16.row.col.f32.f16.f16.f32 "
        "{%0,%1,%2,%3}, {%4,%5,%6,%7}, {%8,%9}, {%0,%1,%2,%3};"
        : "+f"(d[0]), "+f"(d[1]), "+f"(d[2]), "+f"(d[3])
        : "r"(a[0]), "r"(a[1]), "r"(a[2]), "r"(a[3]), "r"(b0), "r"(b1));
}
__device__ __forceinline__ uint32_t pack_h2(float lo, float hi) {
    uint32_t r;
    asm("cvt.rn.f16x2.f32 %0, %1, %2;" : "=r"(r) : "f"(hi), "f"(lo));
    return r;
}

// ---------------- conversion kernels ----------------
__global__ void cvt_split_h(const float* __restrict__ s,
                            __half* __restrict__ hi, __half* __restrict__ lo, int n4)
{
    int i = blockIdx.x * blockDim.x + threadIdx.x;
    if (i >= n4) return;
    float4 v = *(const float4*)(s + (size_t)i * 4);
    __half h0 = __float2half_rn(v.x), h1 = __float2half_rn(v.y);
    __half h2 = __float2half_rn(v.z), h3 = __float2half_rn(v.w);
    *(__half2*)(hi + (size_t)i * 4)     = __halves2half2(h0, h1);
    *(__half2*)(hi + (size_t)i * 4 + 2) = __halves2half2(h2, h3);
    *(__half2*)(lo + (size_t)i * 4)     = __halves2half2(
        __float2half_rn(v.x - __half2float(h0)), __float2half_rn(v.y - __half2float(h1)));
    *(__half2*)(lo + (size_t)i * 4 + 2) = __halves2half2(
        __float2half_rn(v.z - __half2float(h2)), __float2half_rn(v.w - __half2float(h3)));
}
__global__ void cvt_h(const float* __restrict__ s, __half* __restrict__ d, int n4)
{
    int i = blockIdx.x * blockDim.x + threadIdx.x;
    if (i >= n4) return;
    float4 v = *(const float4*)(s + (size_t)i * 4);
    *(__half2*)(d + (size_t)i * 4)     = __halves2half2(__float2half_rn(v.x), __float2half_rn(v.y));
    *(__half2*)(d + (size_t)i * 4 + 2) = __halves2half2(__float2half_rn(v.z), __float2half_rn(v.w));
}

// ---------------- mma.sync GEMM (R9 mainloop) + fused epilogues ----------------
// C = (Ahi+Alo) * Bh^T via 2 K-passes (pass0: Ahi, pass1: Alo), same accumulators.
// mode 0: fp32 out to Cf.
// mode 1 (q+lat): col<2048 -> rope -> (O1h,O1l); col>=2048 -> split -> (O2h,O2l)
// mode 2 (k+v):   col<128  -> rope -> O1h;      col>=128  -> cvt -> O2h
#define GBK 32
#define GSTG 3
#define GTB 8192
#define GM_SMEM (2 * GSTG * GTB)

__global__ __launch_bounds__(256, 2) void gemm_f16x2(
    const __half* __restrict__ Ahi, const __half* __restrict__ Alo,
    const __half* __restrict__ Bh, float* __restrict__ Cf,
    __half* __restrict__ O1h, __half* __restrict__ O1l,
    __half* __restrict__ O2h, __half* __restrict__ O2l,
    const float* __restrict__ cs, const float* __restrict__ sn,
    int N, int K, int mode)
{
    extern __shared__ char smraw[];
    const uint32_t sA = smem_u32(smraw);
    const uint32_t sB = sA + GSTG * GTB;

    const int tid  = threadIdx.x;
    const int wid  = tid >> 5;
    const int lane = tid & 31;
    const int wm = wid >> 2;
    const int wn = wid & 3;
    const int n0 = blockIdx.x * 128;
    const int m0 = blockIdx.y * 128;

    const int KB = K / GBK;
    const int total = 2 * KB;

    float acc[4][4][4];
#pragma unroll
    for (int i = 0; i < 4; i++)
#pragma unroll
        for (int j = 0; j < 4; j++)
#pragma unroll
            for (int u = 0; u < 4; u++) acc[i][j][u] = 0.f;

    auto load_stage = [&](int j, int s) {
        const int kc = (j >= KB) ? (j - KB) : j;
        const __half* A = (j >= KB) ? Alo : Ahi;
        const uint32_t as = sA + (uint32_t)s * GTB;
        const uint32_t bs = sB + (uint32_t)s * GTB;
#pragma unroll
        for (int i = 0; i < 2; i++) {
            int ch  = tid + i * 256;
            int row = ch >> 2;
            int c   = ch & 3;
            int csw = c ^ ((row >> 1) & 3);
            uint32_t off = (uint32_t)(row * 64 + csw * 16);
            cp_async16(as + off, A  + (size_t)(m0 + row) * K + kc * GBK + c * 8);
            cp_async16(bs + off, Bh + (size_t)(n0 + row) * K + kc * GBK + c * 8);
        }
    };

    load_stage(0, 0); CP_COMMIT();
    load_stage(1, 1); CP_COMMIT();

    for (int j = 0; j < total; j++) {
        const int s = j % GSTG;
        CP_WAIT1();
        __syncthreads();
        if (j + 2 < total) load_stage(j + 2, (j + 2) % GSTG);
        CP_COMMIT();

        const uint32_t as = sA + (uint32_t)s * GTB;
        const uint32_t bs = sB + (uint32_t)s * GTB;
#pragma unroll
        for (int kk = 0; kk < 2; kk++) {
            uint32_t a[4][4], b[2][4];
#pragma unroll
            for (int mt = 0; mt < 4; mt++) {
                int row = wm * 64 + mt * 16 + (lane & 15);
                int cc  = kk * 2 + (lane >> 4);
                int csw = cc ^ ((row >> 1) & 3);
                ldm_x4(a[mt][0], a[mt][1], a[mt][2], a[mt][3],
                       as + (uint32_t)(row * 64 + csw * 16));
            }
#pragma unroll
            for (int np = 0; np < 2; np++) {
                int row = wn * 32 + np * 16 + (lane & 15);
                int cc  = kk * 2 + (lane >> 4);
                int csw = cc ^ ((row >> 1) & 3);
                ldm_x4(b[np][0], b[np][1], b[np][2], b[np][3],
                       bs + (uint32_t)(row * 64 + csw * 16));
            }
#pragma unroll
            for (int mt = 0; mt < 4; mt++)
#pragma unroll
                for (int nt = 0; nt < 4; nt++)
                    mma16816(acc[mt][nt], a[mt],
                             b[nt >> 1][nt & 1], b[nt >> 1][(nt & 1) + 2]);
        }
        __syncthreads();
    }

    // ---- fused epilogue ----
    const int r0g = m0 + wm * 64 + (lane >> 2);
    const int c0g = n0 + wn * 32 + (lane & 3) * 2;
#pragma unroll
    for (int mt = 0; mt < 4; mt++)
#pragma unroll
        for (int nt = 0; nt < 4; nt++)
#pragma unroll
            for (int u = 0; u < 2; u++) {
                const int rg = r0g + mt * 16 + u * 8;
                const int cg = c0g + nt * 8;
                float v0 = acc[mt][nt][u * 2];
                float v1 = acc[mt][nt][u * 2 + 1];
                if (mode == 0) {
                    *(float2*)(Cf + (size_t)rg * N + cg) = make_float2(v0, v1);
                } else if (mode == 1) {
                    const int t = rg & (T_ - 1);
                    if (cg < C_) {
                        int jj = (cg & 127) >> 1;
                        float c = cs[t * 64 + jj], s = sn[t * 64 + jj];
                        float o0 = v0 * c - v1 * s;
                        float o1 = v0 * s + v1 * c;
                        __half h0 = __float2half_rn(o0), h1 = __float2half_rn(o1);
                        size_t o = (size_t)rg * C_ + cg;
                        *(__half2*)(O1h + o) = __halves2half2(h0, h1);
                        *(__half2*)(O1l + o) = __halves2half2(
                            __float2half_rn(o0 - __half2float(h0)),
                            __float2half_rn(o1 - __half2float(h1)));
                    } else {
                        __half h0 = __float2half_rn(v0), h1 = __float2half_rn(v1);
                        size_t o = (size_t)rg * L_ + (cg - C_);
                        *(__half2*)(O2h + o) = __halves2half2(h0, h1);
                        *(__half2*)(O2l + o) = __halves2half2(
                            __float2half_rn(v0 - __half2float(h0)),
                            __float2half_rn(v1 - __half2float(h1)));
                    }
                } else {
                    const int t = rg & (T_ - 1);
                    if (cg < D_) {
                        int jj = cg >> 1;
                        float c = cs[t * 64 + jj], s = sn[t * 64 + jj];
                        float o0 = v0 * c - v1 * s;
                        float o1 = v0 * s + v1 * c;
                        *(__half2*)(O1h + (size_t)rg * D_ + cg) =
                            __halves2half2(__float2half_rn(o0), __float2half_rn(o1));
                    } else {
                        *(__half2*)(O2h + (size_t)rg * D_ + (cg - D_)) =
                            __halves2half2(__float2half_rn(v0), __float2half_rn(v1));
                    }
                }
            }
}

// ---------------- mma.sync flash attention (fp16, 2-pass QK, 2-pass PV) ----------------
#define AST 136
#define QT_B (128 * AST * 2)
#define KT_B (64 * AST * 2)
#define STG_B (2 * KT_B)
#define ATT_SMEM (2 * QT_B + 2 * STG_B)

__global__ __launch_bounds__(256, 1) void attn_mma(
    const __half* __restrict__ qhi, const __half* __restrict__ qlo,
    const __half* __restrict__ kh, const __half* __restrict__ vh,
    __half* __restrict__ yhi, __half* __restrict__ ylo)
{
    extern __shared__ char smraw[];
    const uint32_t sQhi = smem_u32(smraw);
    const uint32_t sQlo = sQhi + QT_B;
    const uint32_t sStg = sQlo + QT_B;

    const int tid  = threadIdx.x;
    const int wid  = tid >> 5;
    const int lane = tid & 31;
    const int qt = (T_ / 128 - 1) - blockIdx.x;
    const int h  = blockIdx.y, b = blockIdx.z;
    const int t0 = qt * 128;
    const int jmax = 2 * qt + 1;
    const float scale = 0.08838834764831845f;

    {
        const size_t qb = (((size_t)b * T_ + t0) * H_ + h) * D_;
#pragma unroll
        for (int i = 0; i < 8; i++) {
            int ch  = tid + i * 256;
            int row = ch >> 4;
            int c16 = ch & 15;
            uint32_t doff = (uint32_t)(row * AST + c16 * 8) * 2;
            size_t   soff = qb + (size_t)row * (H_ * D_) + c16 * 8;
            cp_async16(sQhi + doff, qhi + soff);
            cp_async16(sQlo + doff, qlo + soff);
        }
    }
    auto load_stage = [&](int j, int s) {
        const uint32_t sb = sStg + (uint32_t)s * STG_B;
        const size_t   gb = ((size_t)b * T_ + j * 64) * D_;
#pragma unroll
        for (int i = 0; i < 4; i++) {
            int ch  = tid + i * 256;
            int row = ch >> 4;
            int c16 = ch & 15;
            uint32_t doff = (uint32_t)(row * AST + c16 * 8) * 2;
            size_t   soff = gb + (size_t)row * D_ + c16 * 8;
            cp_async16(sb + doff,        kh + soff);
            cp_async16(sb + KT_B + doff, vh + soff);
        }
    };
    load_stage(0, 0); CP_COMMIT();
    load_stage(1, 1); CP_COMMIT();

    float m0 = -3.0e38f, m1 = -3.0e38f, l0 = 0.f, l1 = 0.f;
    float yacc[16][4];
#pragma unroll
    for (int nt = 0; nt < 16; nt++)
#pragma unroll
        for (int u = 0; u < 4; u++) yacc[nt][u] = 0.f;

    const int rloc = wid * 16 + (lane >> 2);

    for (int j = 0; j <= jmax; j++) {
        const int s = j & 1;
        if (j < jmax) { CP_WAIT1(); } else { CP_WAIT0(); }
        __syncthreads();
        const uint32_t sKh = sStg + (uint32_t)s * STG_B;
        const uint32_t sVh = sKh + KT_B;

        float sacc[8][4];
#pragma unroll
        for (int nt = 0; nt < 8; nt++)
#pragma unroll
            for (int u = 0; u < 4; u++) sacc[nt][u] = 0.f;

#pragma unroll
        for (int kk = 0; kk < 8; kk++) {
            uint32_t ah[4], al[4], bb[4][4];
            {
                int row = wid * 16 + (lane & 15);
                int col = kk * 16 + (lane >> 4) * 8;
                uint32_t off = (uint32_t)(row * AST + col) * 2;
                ldm_x4(ah[0], ah[1], ah[2], ah[3], sQhi + off);
                ldm_x4(al[0], al[1], al[2], al[3], sQlo + off);
            }
#pragma unroll
            for (int nt2 = 0; nt2 < 4; nt2++) {
                int row = nt2 * 16 + (lane & 15);
                int col = kk * 16 + (lane >> 4) * 8;
                ldm_x4(bb[nt2][0], bb[nt2][1], bb[nt2][2], bb[nt2][3],
                       sKh + (uint32_t)(row * AST + col) * 2);
            }
#pragma unroll
            for (int nt = 0; nt < 8; nt++) {
                mma16816(sacc[nt], ah, bb[nt >> 1][nt & 1], bb[nt >> 1][(nt & 1) + 2]);
                mma16816(sacc[nt], al, bb[nt >> 1][nt & 1], bb[nt >> 1][(nt & 1) + 2]);
            }
        }

        const bool need_mask = (j >= jmax - 1);
#pragma unroll
        for (int nt = 0; nt < 8; nt++)
#pragma unroll
            for (int u = 0; u < 4; u++) {
                float v = sacc[nt][u] * scale;
                if (need_mask) {
                    int rg = t0 + rloc + (u >> 1) * 8;
                    int cg = j * 64 + nt * 8 + (lane & 3) * 2 + (u & 1);
                    if (cg > rg) v = -1.0e30f;
                }
                sacc[nt][u] = v;
            }

        float rx0 = -3.0e38f, rx1 = -3.0e38f;
#pragma unroll
        for (int nt = 0; nt < 8; nt++) {
            rx0 = fmaxf(rx0, fmaxf(sacc[nt][0], sacc[nt][1]));
            rx1 = fmaxf(rx1, fmaxf(sacc[nt][2], sacc[nt][3]));
        }
        rx0 = fmaxf(rx0, __shfl_xor_sync(0xffffffffu, rx0, 1));
        rx0 = fmaxf(rx0, __shfl_xor_sync(0xffffffffu, rx0, 2));
        rx1 = fmaxf(rx1, __shfl_xor_sync(0xffffffffu, rx1, 1));
        rx1 = fmaxf(rx1, __shfl_xor_sync(0xffffffffu, rx1, 2));
        float mn0 = fmaxf(m0, rx0), mn1 = fmaxf(m1, rx1);
        float sc0 = __expf(m0 - mn0), sc1 = __expf(m1 - mn1);
        m0 = mn0; m1 = mn1;

        float rs0 = 0.f, rs1 = 0.f;
#pragma unroll
        for (int nt = 0; nt < 8; nt++) {
            sacc[nt][0] = __expf(sacc[nt][0] - mn0);
            sacc[nt][1] = __expf(sacc[nt][1] - mn0);
            sacc[nt][2] = __expf(sacc[nt][2] - mn1);
            sacc[nt][3] = __expf(sacc[nt][3] - mn1);
            rs0 += sacc[nt][0] + sacc[nt][1];
            rs1 += sacc[nt][2] + sacc[nt][3];
        }
        rs0 += __shfl_xor_sync(0xffffffffu, rs0, 1);
        rs0 += __shfl_xor_sync(0xffffffffu, rs0, 2);
        rs1 += __shfl_xor_sync(0xffffffffu, rs1, 1);
        rs1 += __shfl_xor_sync(0xffffffffu, rs1, 2);
        l0 = l0 * sc0 + rs0;
        l1 = l1 * sc1 + rs1;

#pragma unroll
        for (int nt = 0; nt < 16; nt++) {
            yacc[nt][0] *= sc0; yacc[nt][1] *= sc0;
            yacc[nt][2] *= sc1; yacc[nt][3] *= sc1;
        }

        uint32_t phiA[4][4], ploA[4][4];
#pragma unroll
        for (int kk2 = 0; kk2 < 4; kk2++) {
            const int ta = 2 * kk2, tb2 = 2 * kk2 + 1;
            float ph[8], pl[8];
            const float* src[2] = { sacc[ta], sacc[tb2] };
#pragma unroll
            for (int q2 = 0; q2 < 2; q2++)
#pragma unroll
                for (int u = 0; u < 4; u++) {
                    float p = src[q2][u];
                    __half hh = __float2half_rn(p);
                    ph[q2 * 4 + u] = __half2float(hh);
                    pl[q2 * 4 + u] = p - ph[q2 * 4 + u];
                }
            phiA[kk2][0] = pack_h2(ph[0], ph[1]);
            phiA[kk2][1] = pack_h2(ph[2], ph[3]);
            phiA[kk2][2] = pack_h2(ph[4], ph[5]);
            phiA[kk2][3] = pack_h2(ph[6], ph[7]);
            ploA[kk2][0] = pack_h2(pl[0], pl[1]);
            ploA[kk2][1] = pack_h2(pl[2], pl[3]);
            ploA[kk2][2] = pack_h2(pl[4], pl[5]);
            ploA[kk2][3] = pack_h2(pl[6], pl[7]);
        }

#pragma unroll
        for (int kk2 = 0; kk2 < 4; kk2++) {
            uint32_t vb[8][4];
#pragma unroll
            for (int nt2 = 0; nt2 < 8; nt2++) {
                int row = kk2 * 16 + (lane & 15);
                int col = nt2 * 16 + (lane >> 4) * 8;
                ldm_x4_t(vb[nt2][0], vb[nt2][1], vb[nt2][2], vb[nt2][3],
                         sVh + (uint32_t)(row * AST + col) * 2);
            }
#pragma unroll
            for (int nt = 0; nt < 16; nt++) {
                mma16816(yacc[nt], phiA[kk2],
                         vb[nt >> 1][(nt & 1) * 2], vb[nt >> 1][(nt & 1) * 2 + 1]);
                mma16816(yacc[nt], ploA[kk2],
                         vb[nt >> 1][(nt & 1) * 2], vb[nt >> 1][(nt & 1) * 2 + 1]);
            }
        }

        __syncthreads();
        if (j + 2 <= jmax) { load_stage(j + 2, s); CP_COMMIT(); }
    }

    const float inv0 = 1.f / l0, inv1 = 1.f / l1;
#pragma unroll
    for (int half = 0; half < 2; half++) {
        const int rg = t0 + rloc + half * 8;
        const float inv = half ? inv1 : inv0;
        __half* ph = yhi + (((size_t)b * T_ + rg) * H_ + h) * D_;
        __half* pl = ylo + (((size_t)b * T_ + rg) * H_ + h) * D_;
#pragma unroll
        for (int nt = 0; nt < 16; nt++) {
            int cg = nt * 8 + (lane & 3) * 2;
            float v0 = yacc[nt][half * 2]     * inv;
            float v1 = yacc[nt][half * 2 + 1] * inv;
            __half h0 = __float2half_rn(v0), h1 = __float2half_rn(v1);
            *(__half2*)(ph + cg) = __halves2half2(h0, h1);
            *(__half2*)(pl + cg) = __halves2half2(
                __float2half_rn(v0 - __half2float(h0)),
                __float2half_rn(v1 - __half2float(h1)));
        }
    }
}

// ---------------- host launcher ----------------
extern "C" void kernel_launch(void* const* d_in, const int* in_sizes, int n_in,
                              void* d_out, int out_size)
{
    const float* x     = (const float*)d_in[0];
    const float* fcos  = (const float*)d_in[1];
    const float* fsin  = (const float*)d_in[2];
    const float* wq    = (const float*)d_in[3];
    const float* wkv   = (const float*)d_in[4];
    const float* wk_up = (const float*)d_in[5];
    const float* wv_up = (const float*)d_in[6];
    const float* wo    = (const float*)d_in[7];
    float* out = (float*)d_out;

    __half *xhi, *xlo, *qh, *ql, *lhi, *llo, *kh, *vh, *wqkvh, *wuph, *woh;
    cudaGetSymbolAddress((void**)&xhi,   g_xhi);
    cudaGetSymbolAddress((void**)&xlo,   g_xlo);
    cudaGetSymbolAddress((void**)&qh,    g_qh);
    cudaGetSymbolAddress((void**)&ql,    g_ql);
    cudaGetSymbolAddress((void**)&lhi,   g_lhi);
    cudaGetSymbolAddress((void**)&llo,   g_llo);
    cudaGetSymbolAddress((void**)&kh,    g_kh);
    cudaGetSymbolAddress((void**)&vh,    g_vh);
    cudaGetSymbolAddress((void**)&wqkvh, g_wqkvh);
    cudaGetSymbolAddress((void**)&wuph,  g_wuph);
    cudaGetSymbolAddress((void**)&woh,   g_woh);

    cudaFuncSetAttribute(gemm_f16x2,
                         cudaFuncAttributeMaxDynamicSharedMemorySize, GM_SMEM);
    cudaFuncSetAttribute(attn_mma,
                         cudaFuncAttributeMaxDynamicSharedMemorySize, ATT_SMEM);

    // conversions
    cvt_split_h<<<(BT_*C_/4)/256, 256>>>(x, xhi, xlo, BT_*C_/4);
    cvt_h<<<(H_*D_*C_/4)/256, 256>>>(wq, wqkvh, H_*D_*C_/4);
    cvt_h<<<(L_*C_/4)/256, 256>>>(wkv, wqkvh + (size_t)H_*D_*C_, L_*C_/4);
    cvt_h<<<(D_*L_/4)/256, 256>>>(wk_up, wuph, D_*L_/4);
    cvt_h<<<(D_*L_/4)/256, 256>>>(wv_up, wuph + (size_t)D_*L_, D_*L_/4);
    cvt_h<<<(C_*H_*D_/4)/256, 256>>>(wo, woh, C_*H_*D_/4);

    // q+lat projection with fused rope+split epilogue
    gemm_f16x2<<<dim3(NQL/128, BT_/128), 256, GM_SMEM>>>(
        xhi, xlo, wqkvh, nullptr, qh, ql, lhi, llo, fcos, fsin, NQL, C_, 1);
    // k+v up-projection with fused rope/cvt epilogue
    gemm_f16x2<<<dim3(NKV/128, BT_/128), 256, GM_SMEM>>>(
        lhi, llo, wuph, nullptr, kh, nullptr, vh, nullptr, fcos, fsin, NKV, L_, 2);

    // attention: y splits overwrite x splits (dead after q+lat GEMM)
    attn_mma<<<dim3(T_/128, H_, B_), 256, ATT_SMEM>>>(
        qh, ql, kh, vh, xhi, xlo);

    // output projection, fp32 epilogue
    gemm_f16x2<<<dim3(C_/128, BT_/128), 256, GM_SMEM>>>(
        xhi, xlo, woh, out, nullptr, nullptr, nullptr, nullptr,
        nullptr, nullptr, C_, H_*D_, 0);
}

// round 13
// speedup vs baseline: 2.2451x; 1.3476x over previous
#include <cuda_runtime.h>
#include <cuda_fp16.h>
#include <math.h>
#include <stdint.h>

#define B_ 4
#define T_ 2048
#define C_ 2048
#define H_ 16
#define D_ 128
#define L_ 512
#define BT_ (B_*T_)
#define NQL 2560
#define NKV 256

// ---------------- scratch ----------------
__device__ __half g_xhi[(size_t)BT_ * C_];      // x hi split -> (after attn) y fp16
__device__ __half g_xlo[(size_t)BT_ * C_];      // x lo split
__device__ __half g_qh[(size_t)BT_ * C_];       // rope(q) fp16 (single)
__device__ __half g_lhi[(size_t)BT_ * L_];
__device__ __half g_llo[(size_t)BT_ * L_];
__device__ __half g_kh[(size_t)BT_ * D_];
__device__ __half g_vh[(size_t)BT_ * D_];
__device__ __half g_wqkvh[(size_t)NQL * C_];
__device__ __half g_wuph[(size_t)NKV * L_];
__device__ __half g_woh[(size_t)C_ * H_ * D_];

// ---------------- helpers ----------------
__device__ __forceinline__ uint32_t smem_u32(const void* p) {
    uint32_t a;
    asm("{ .reg .u64 t; cvta.to.shared.u64 t, %1; cvt.u32.u64 %0, t; }"
        : "=r"(a) : "l"(p));
    return a;
}
__device__ __forceinline__ void cp_async16(uint32_t dst, const void* src) {
    asm volatile("cp.async.cg.shared.global [%0], [%1], 16;"
                 :: "r"(dst), "l"(src) : "memory");
}
#define CP_COMMIT() asm volatile("cp.async.commit_group;" ::: "memory")
#define CP_WAIT1()  asm volatile("cp.async.wait_group 1;" ::: "memory")
#define CP_WAIT0()  asm volatile("cp.async.wait_group 0;" ::: "memory")

__device__ __forceinline__ void ldm_x4(uint32_t& r0, uint32_t& r1,
                                       uint32_t& r2, uint32_t& r3, uint32_t a) {
    asm volatile("ldmatrix.sync.aligned.m8n8.x4.shared.b16 {%0,%1,%2,%3}, [%4];"
                 : "=r"(r0), "=r"(r1), "=r"(r2), "=r"(r3) : "r"(a));
}
__device__ __forceinline__ void ldm_x4_t(uint32_t& r0, uint32_t& r1,
                                         uint32_t& r2, uint32_t& r3, uint32_t a) {
    asm volatile("ldmatrix.sync.aligned.m8n8.x4.trans.shared.b16 {%0,%1,%2,%3}, [%4];"
                 : "=r"(r0), "=r"(r1), "=r"(r2), "=r"(r3) : "r"(a));
}
__device__ __forceinline__ void mma16816(float* d, const uint32_t* a,
                                         uint32_t b0, uint32_t b1) {
    asm volatile(
        "mma.sync.aligned.m16n8k16.row.col.f32.f16.f16.f32 "
        "{%0,%1,%2,%3}, {%4,%5,%6,%7}, {%8,%9}, {%0,%1,%2,%3};"
        : "+f"(d[0]), "+f"(d[1]), "+f"(d[2]), "+f"(d[3])
        : "r"(a[0]), "r"(a[1]), "r"(a[2]), "r"(a[3]), "r"(b0), "r"(b1));
}
__device__ __forceinline__ uint32_t pack_h2(float lo, float hi) {
    uint32_t r;
    asm("cvt.rn.f16x2.f32 %0, %1, %2;" : "=r"(r) : "f"(hi), "f"(lo));
    return r;
}

// ---------------- conversion kernels ----------------
__global__ void cvt_split_h(const float* __restrict__ s,
                            __half* __restrict__ hi, __half* __restrict__ lo, int n4)
{
    int i = blockIdx.x * blockDim.x + threadIdx.x;
    if (i >= n4) return;
    float4 v = *(const float4*)(s + (size_t)i * 4);
    __half h0 = __float2half_rn(v.x), h1 = __float2half_rn(v.y);
    __half h2 = __float2half_rn(v.z), h3 = __float2half_rn(v.w);
    *(__half2*)(hi + (size_t)i * 4)     = __halves2half2(h0, h1);
    *(__half2*)(hi + (size_t)i * 4 + 2) = __halves2half2(h2, h3);
    *(__half2*)(lo + (size_t)i * 4)     = __halves2half2(
        __float2half_rn(v.x - __half2float(h0)), __float2half_rn(v.y - __half2float(h1)));
    *(__half2*)(lo + (size_t)i * 4 + 2) = __halves2half2(
        __float2half_rn(v.z - __half2float(h2)), __float2half_rn(v.w - __half2float(h3)));
}
__global__ void cvt_h(const float* __restrict__ s, __half* __restrict__ d, int n4)
{
    int i = blockIdx.x * blockDim.x + threadIdx.x;
    if (i >= n4) return;
    float4 v = *(const float4*)(s + (size_t)i * 4);
    *(__half2*)(d + (size_t)i * 4)     = __halves2half2(__float2half_rn(v.x), __float2half_rn(v.y));
    *(__half2*)(d + (size_t)i * 4 + 2) = __halves2half2(__float2half_rn(v.z), __float2half_rn(v.w));
}

// ---------------- mma.sync GEMM (R9 mainloop) + fused epilogues ----------------
// C = A*B^T. npass=2: accumulate Ahi then Alo passes; npass=1: Ahi only.
// mode 0: fp32 out to Cf.
// mode 1 (q+lat): col<2048 -> rope -> O1h (fp16); col>=2048 -> split -> (O2h,O2l)
// mode 2 (k+v):   col<128  -> rope -> O1h;      col>=128  -> cvt -> O2h
#define GBK 32
#define GSTG 3
#define GTB 8192
#define GM_SMEM (2 * GSTG * GTB)

__global__ __launch_bounds__(256, 2) void gemm_f16x2(
    const __half* __restrict__ Ahi, const __half* __restrict__ Alo,
    const __half* __restrict__ Bh, float* __restrict__ Cf,
    __half* __restrict__ O1h,
    __half* __restrict__ O2h, __half* __restrict__ O2l,
    const float* __restrict__ cs, const float* __restrict__ sn,
    int N, int K, int mode, int npass)
{
    extern __shared__ char smraw[];
    const uint32_t sA = smem_u32(smraw);
    const uint32_t sB = sA + GSTG * GTB;

    const int tid  = threadIdx.x;
    const int wid  = tid >> 5;
    const int lane = tid & 31;
    const int wm = wid >> 2;
    const int wn = wid & 3;
    const int n0 = blockIdx.x * 128;
    const int m0 = blockIdx.y * 128;

    const int KB = K / GBK;
    const int total = npass * KB;

    float acc[4][4][4];
#pragma unroll
    for (int i = 0; i < 4; i++)
#pragma unroll
        for (int j = 0; j < 4; j++)
#pragma unroll
            for (int u = 0; u < 4; u++) acc[i][j][u] = 0.f;

    auto load_stage = [&](int j, int s) {
        const int kc = (j >= KB) ? (j - KB) : j;
        const __half* A = (j >= KB) ? Alo : Ahi;
        const uint32_t as = sA + (uint32_t)s * GTB;
        const uint32_t bs = sB + (uint32_t)s * GTB;
#pragma unroll
        for (int i = 0; i < 2; i++) {
            int ch  = tid + i * 256;
            int row = ch >> 2;
            int c   = ch & 3;
            int csw = c ^ ((row >> 1) & 3);
            uint32_t off = (uint32_t)(row * 64 + csw * 16);
            cp_async16(as + off, A  + (size_t)(m0 + row) * K + kc * GBK + c * 8);
            cp_async16(bs + off, Bh + (size_t)(n0 + row) * K + kc * GBK + c * 8);
        }
    };

    load_stage(0, 0); CP_COMMIT();
    load_stage(1, 1); CP_COMMIT();

    for (int j = 0; j < total; j++) {
        const int s = j % GSTG;
        CP_WAIT1();
        __syncthreads();
        if (j + 2 < total) load_stage(j + 2, (j + 2) % GSTG);
        CP_COMMIT();

        const uint32_t as = sA + (uint32_t)s * GTB;
        const uint32_t bs = sB + (uint32_t)s * GTB;
#pragma unroll
        for (int kk = 0; kk < 2; kk++) {
            uint32_t a[4][4], b[2][4];
#pragma unroll
            for (int mt = 0; mt < 4; mt++) {
                int row = wm * 64 + mt * 16 + (lane & 15);
                int cc  = kk * 2 + (lane >> 4);
                int csw = cc ^ ((row >> 1) & 3);
                ldm_x4(a[mt][0], a[mt][1], a[mt][2], a[mt][3],
                       as + (uint32_t)(row * 64 + csw * 16));
            }
#pragma unroll
            for (int np = 0; np < 2; np++) {
                int row = wn * 32 + np * 16 + (lane & 15);
                int cc  = kk * 2 + (lane >> 4);
                int csw = cc ^ ((row >> 1) & 3);
                ldm_x4(b[np][0], b[np][1], b[np][2], b[np][3],
                       bs + (uint32_t)(row * 64 + csw * 16));
            }
#pragma unroll
            for (int mt = 0; mt < 4; mt++)
#pragma unroll
                for (int nt = 0; nt < 4; nt++)
                    mma16816(acc[mt][nt], a[mt],
                             b[nt >> 1][nt & 1], b[nt >> 1][(nt & 1) + 2]);
        }
        __syncthreads();
    }

    // ---- fused epilogue ----
    const int r0g = m0 + wm * 64 + (lane >> 2);
    const int c0g = n0 + wn * 32 + (lane & 3) * 2;
#pragma unroll
    for (int mt = 0; mt < 4; mt++)
#pragma unroll
        for (int nt = 0; nt < 4; nt++)
#pragma unroll
            for (int u = 0; u < 2; u++) {
                const int rg = r0g + mt * 16 + u * 8;
                const int cg = c0g + nt * 8;
                float v0 = acc[mt][nt][u * 2];
                float v1 = acc[mt][nt][u * 2 + 1];
                if (mode == 0) {
                    *(float2*)(Cf + (size_t)rg * N + cg) = make_float2(v0, v1);
                } else if (mode == 1) {
                    const int t = rg & (T_ - 1);
                    if (cg < C_) {
                        int jj = (cg & 127) >> 1;
                        float c = cs[t * 64 + jj], s = sn[t * 64 + jj];
                        float o0 = v0 * c - v1 * s;
                        float o1 = v0 * s + v1 * c;
                        *(__half2*)(O1h + (size_t)rg * C_ + cg) =
                            __halves2half2(__float2half_rn(o0), __float2half_rn(o1));
                    } else {
                        __half h0 = __float2half_rn(v0), h1 = __float2half_rn(v1);
                        size_t o = (size_t)rg * L_ + (cg - C_);
                        *(__half2*)(O2h + o) = __halves2half2(h0, h1);
                        *(__half2*)(O2l + o) = __halves2half2(
                            __float2half_rn(v0 - __half2float(h0)),
                            __float2half_rn(v1 - __half2float(h1)));
                    }
                } else {
                    const int t = rg & (T_ - 1);
                    if (cg < D_) {
                        int jj = cg >> 1;
                        float c = cs[t * 64 + jj], s = sn[t * 64 + jj];
                        float o0 = v0 * c - v1 * s;
                        float o1 = v0 * s + v1 * c;
                        *(__half2*)(O1h + (size_t)rg * D_ + cg) =
                            __halves2half2(__float2half_rn(o0), __float2half_rn(o1));
                    } else {
                        *(__half2*)(O2h + (size_t)rg * D_ + (cg - D_)) =
                            __halves2half2(__float2half_rn(v0), __float2half_rn(v1));
                    }
                }
            }
}

// ---------------- mma.sync flash attention (fp16, single-pass QK and PV) ----------------
#define AST 136
#define QT_B (128 * AST * 2)
#define KT_B (64 * AST * 2)
#define STG_B (2 * KT_B)
#define ATT_SMEM (QT_B + 2 * STG_B)   // 104448

__global__ __launch_bounds__(256, 1) void attn_mma(
    const __half* __restrict__ qh, const __half* __restrict__ kh,
    const __half* __restrict__ vh, __half* __restrict__ yh)
{
    extern __shared__ char smraw[];
    const uint32_t sQ   = smem_u32(smraw);
    const uint32_t sStg = sQ + QT_B;

    const int tid  = threadIdx.x;
    const int wid  = tid >> 5;
    const int lane = tid & 31;
    const int qt = (T_ / 128 - 1) - blockIdx.x;
    const int h  = blockIdx.y, b = blockIdx.z;
    const int t0 = qt * 128;
    const int jmax = 2 * qt + 1;
    const float scale = 0.08838834764831845f;

    {
        const size_t qb = (((size_t)b * T_ + t0) * H_ + h) * D_;
#pragma unroll
        for (int i = 0; i < 8; i++) {
            int ch  = tid + i * 256;
            int row = ch >> 4;
            int c16 = ch & 15;
            uint32_t doff = (uint32_t)(row * AST + c16 * 8) * 2;
            cp_async16(sQ + doff, qh + qb + (size_t)row * (H_ * D_) + c16 * 8);
        }
    }
    auto load_stage = [&](int j, int s) {
        const uint32_t sb = sStg + (uint32_t)s * STG_B;
        const size_t   gb = ((size_t)b * T_ + j * 64) * D_;
#pragma unroll
        for (int i = 0; i < 4; i++) {
            int ch  = tid + i * 256;
            int row = ch >> 4;
            int c16 = ch & 15;
            uint32_t doff = (uint32_t)(row * AST + c16 * 8) * 2;
            size_t   soff = gb + (size_t)row * D_ + c16 * 8;
            cp_async16(sb + doff,        kh + soff);
            cp_async16(sb + KT_B + doff, vh + soff);
        }
    };
    load_stage(0, 0); CP_COMMIT();
    load_stage(1, 1); CP_COMMIT();

    float m0 = -3.0e38f, m1 = -3.0e38f, l0 = 0.f, l1 = 0.f;
    float yacc[16][4];
#pragma unroll
    for (int nt = 0; nt < 16; nt++)
#pragma unroll
        for (int u = 0; u < 4; u++) yacc[nt][u] = 0.f;

    const int rloc = wid * 16 + (lane >> 2);

    for (int j = 0; j <= jmax; j++) {
        const int s = j & 1;
        if (j < jmax) { CP_WAIT1(); } else { CP_WAIT0(); }
        __syncthreads();
        const uint32_t sKh = sStg + (uint32_t)s * STG_B;
        const uint32_t sVh = sKh + KT_B;

        float sacc[8][4];
#pragma unroll
        for (int nt = 0; nt < 8; nt++)
#pragma unroll
            for (int u = 0; u < 4; u++) sacc[nt][u] = 0.f;

#pragma unroll
        for (int kk = 0; kk < 8; kk++) {
            uint32_t a[4], bb[4][4];
            {
                int row = wid * 16 + (lane & 15);
                int col = kk * 16 + (lane >> 4) * 8;
                ldm_x4(a[0], a[1], a[2], a[3],
                       sQ + (uint32_t)(row * AST + col) * 2);
            }
#pragma unroll
            for (int nt2 = 0; nt2 < 4; nt2++) {
                int row = nt2 * 16 + (lane & 15);
                int col = kk * 16 + (lane >> 4) * 8;
                ldm_x4(bb[nt2][0], bb[nt2][1], bb[nt2][2], bb[nt2][3],
                       sKh + (uint32_t)(row * AST + col) * 2);
            }
#pragma unroll
            for (int nt = 0; nt < 8; nt++)
                mma16816(sacc[nt], a,
                         bb[nt >> 1][nt & 1], bb[nt >> 1][(nt & 1) + 2]);
        }

        const bool need_mask = (j >= jmax - 1);
#pragma unroll
        for (int nt = 0; nt < 8; nt++)
#pragma unroll
            for (int u = 0; u < 4; u++) {
                float v = sacc[nt][u] * scale;
                if (need_mask) {
                    int rg = t0 + rloc + (u >> 1) * 8;
                    int cg = j * 64 + nt * 8 + (lane & 3) * 2 + (u & 1);
                    if (cg > rg) v = -1.0e30f;
                }
                sacc[nt][u] = v;
            }

        float rx0 = -3.0e38f, rx1 = -3.0e38f;
#pragma unroll
        for (int nt = 0; nt < 8; nt++) {
            rx0 = fmaxf(rx0, fmaxf(sacc[nt][0], sacc[nt][1]));
            rx1 = fmaxf(rx1, fmaxf(sacc[nt][2], sacc[nt][3]));
        }
        rx0 = fmaxf(rx0, __shfl_xor_sync(0xffffffffu, rx0, 1));
        rx0 = fmaxf(rx0, __shfl_xor_sync(0xffffffffu, rx0, 2));
        rx1 = fmaxf(rx1, __shfl_xor_sync(0xffffffffu, rx1, 1));
        rx1 = fmaxf(rx1, __shfl_xor_sync(0xffffffffu, rx1, 2));
        float mn0 = fmaxf(m0, rx0), mn1 = fmaxf(m1, rx1);
        float sc0 = __expf(m0 - mn0), sc1 = __expf(m1 - mn1);
        m0 = mn0; m1 = mn1;

        float rs0 = 0.f, rs1 = 0.f;
#pragma unroll
        for (int nt = 0; nt < 8; nt++) {
            sacc[nt][0] = __expf(sacc[nt][0] - mn0);
            sacc[nt][1] = __expf(sacc[nt][1] - mn0);
            sacc[nt][2] = __expf(sacc[nt][2] - mn1);
            sacc[nt][3] = __expf(sacc[nt][3] - mn1);
            rs0 += sacc[nt][0] + sacc[nt][1];
            rs1 += sacc[nt][2] + sacc[nt][3];
        }
        rs0 += __shfl_xor_sync(0xffffffffu, rs0, 1);
        rs0 += __shfl_xor_sync(0xffffffffu, rs0, 2);
        rs1 += __shfl_xor_sync(0xffffffffu, rs1, 1);
        rs1 += __shfl_xor_sync(0xffffffffu, rs1, 2);
        l0 = l0 * sc0 + rs0;
        l1 = l1 * sc1 + rs1;

#pragma unroll
        for (int nt = 0; nt < 16; nt++) {
            yacc[nt][0] *= sc0; yacc[nt][1] *= sc0;
            yacc[nt][2] *= sc1; yacc[nt][3] *= sc1;
        }

        // P a-fragments (single fp16)
        uint32_t pA[4][4];
#pragma unroll
        for (int kk2 = 0; kk2 < 4; kk2++) {
            const float* s0 = sacc[2 * kk2];
            const float* s1 = sacc[2 * kk2 + 1];
            pA[kk2][0] = pack_h2(s0[0], s0[1]);
            pA[kk2][1] = pack_h2(s0[2], s0[3]);
            pA[kk2][2] = pack_h2(s1[0], s1[1]);
            pA[kk2][3] = pack_h2(s1[2], s1[3]);
        }

#pragma unroll
        for (int kk2 = 0; kk2 < 4; kk2++) {
            uint32_t vb[8][4];
#pragma unroll
            for (int nt2 = 0; nt2 < 8; nt2++) {
                int row = kk2 * 16 + (lane & 15);
                int col = nt2 * 16 + (lane >> 4) * 8;
                ldm_x4_t(vb[nt2][0], vb[nt2][1], vb[nt2][2], vb[nt2][3],
                         sVh + (uint32_t)(row * AST + col) * 2);
            }
#pragma unroll
            for (int nt = 0; nt < 16; nt++)
                mma16816(yacc[nt], pA[kk2],
                         vb[nt >> 1][(nt & 1) * 2], vb[nt >> 1][(nt & 1) * 2 + 1]);
        }

        __syncthreads();
        if (j + 2 <= jmax) { load_stage(j + 2, s); CP_COMMIT(); }
    }

    const float inv0 = 1.f / l0, inv1 = 1.f / l1;
#pragma unroll
    for (int half = 0; half < 2; half++) {
        const int rg = t0 + rloc + half * 8;
        const float inv = half ? inv1 : inv0;
        __half* py = yh + (((size_t)b * T_ + rg) * H_ + h) * D_;
#pragma unroll
        for (int nt = 0; nt < 16; nt++) {
            int cg = nt * 8 + (lane & 3) * 2;
            *(__half2*)(py + cg) = __halves2half2(
                __float2half_rn(yacc[nt][half * 2]     * inv),
                __float2half_rn(yacc[nt][half * 2 + 1] * inv));
        }
    }
}

// ---------------- host launcher ----------------
extern "C" void kernel_launch(void* const* d_in, const int* in_sizes, int n_in,
                              void* d_out, int out_size)
{
    const float* x     = (const float*)d_in[0];
    const float* fcos  = (const float*)d_in[1];
    const float* fsin  = (const float*)d_in[2];
    const float* wq    = (const float*)d_in[3];
    const float* wkv   = (const float*)d_in[4];
    const float* wk_up = (const float*)d_in[5];
    const float* wv_up = (const float*)d_in[6];
    const float* wo    = (const float*)d_in[7];
    float* out = (float*)d_out;

    __half *xhi, *xlo, *qh, *lhi, *llo, *kh, *vh, *wqkvh, *wuph, *woh;
    cudaGetSymbolAddress((void**)&xhi,   g_xhi);
    cudaGetSymbolAddress((void**)&xlo,   g_xlo);
    cudaGetSymbolAddress((void**)&qh,    g_qh);
    cudaGetSymbolAddress((void**)&lhi,   g_lhi);
    cudaGetSymbolAddress((void**)&llo,   g_llo);
    cudaGetSymbolAddress((void**)&kh,    g_kh);
    cudaGetSymbolAddress((void**)&vh,    g_vh);
    cudaGetSymbolAddress((void**)&wqkvh, g_wqkvh);
    cudaGetSymbolAddress((void**)&wuph,  g_wuph);
    cudaGetSymbolAddress((void**)&woh,   g_woh);

    cudaFuncSetAttribute(gemm_f16x2,
                         cudaFuncAttributeMaxDynamicSharedMemorySize, GM_SMEM);
    cudaFuncSetAttribute(attn_mma,
                         cudaFuncAttributeMaxDynamicSharedMemorySize, ATT_SMEM);

    // conversions
    cvt_split_h<<<(BT_*C_/4)/256, 256>>>(x, xhi, xlo, BT_*C_/4);
    cvt_h<<<(H_*D_*C_/4)/256, 256>>>(wq, wqkvh, H_*D_*C_/4);
    cvt_h<<<(L_*C_/4)/256, 256>>>(wkv, wqkvh + (size_t)H_*D_*C_, L_*C_/4);
    cvt_h<<<(D_*L_/4)/256, 256>>>(wk_up, wuph, D_*L_/4);
    cvt_h<<<(D_*L_/4)/256, 256>>>(wv_up, wuph + (size_t)D_*L_, D_*L_/4);
    cvt_h<<<(C_*H_*D_/4)/256, 256>>>(wo, woh, C_*H_*D_/4);

    // q+lat projection (2-pass A split): q -> rope fp16, lat -> hi/lo split
    gemm_f16x2<<<dim3(NQL/128, BT_/128), 256, GM_SMEM>>>(
        xhi, xlo, wqkvh, nullptr, qh, lhi, llo, fcos, fsin, NQL, C_, 1, 2);
    // k+v up-projection (2-pass lat split): k -> rope fp16, v -> fp16
    gemm_f16x2<<<dim3(NKV/128, BT_/128), 256, GM_SMEM>>>(
        lhi, llo, wuph, nullptr, kh, vh, nullptr, fcos, fsin, NKV, L_, 2, 2);

    // attention (single-pass): y fp16 overwrites xhi (dead after q+lat GEMM)
    attn_mma<<<dim3(T_/128, H_, B_), 256, ATT_SMEM>>>(qh, kh, vh, xhi);

    // output projection (single-pass, y fp16), fp32 epilogue
    gemm_f16x2<<<dim3(C_/128, BT_/128), 256, GM_SMEM>>>(
        xhi, xhi, woh, out, nullptr, nullptr, nullptr,
        nullptr, nullptr, C_, H_*D_, 0, 1);
}

// round 14
// speedup vs baseline: 2.9264x; 1.3035x over previous
#include <cuda_runtime.h>
#include <cuda_fp16.h>
#include <math.h>
#include <stdint.h>

#define B_ 4
#define T_ 2048
#define C_ 2048
#define H_ 16
#define D_ 128
#define L_ 512
#define BT_ (B_*T_)
#define NQL 2560
#define NKV 256

// ---------------- scratch ----------------
__device__ __half g_xh[(size_t)BT_ * C_];       // x fp16 -> (after attn) y fp16
__device__ __half g_qh[(size_t)BT_ * C_];       // rope(q) fp16
__device__ __half g_lhi[(size_t)BT_ * L_];
__device__ __half g_llo[(size_t)BT_ * L_];
__device__ __half g_kh[(size_t)BT_ * D_];
__device__ __half g_vh[(size_t)BT_ * D_];
__device__ __half g_wqkvh[(size_t)NQL * C_];
__device__ __half g_wuph[(size_t)NKV * L_];
__device__ __half g_woh[(size_t)C_ * H_ * D_];

// ---------------- helpers ----------------
__device__ __forceinline__ uint32_t smem_u32(const void* p) {
    uint32_t a;
    asm("{ .reg .u64 t; cvta.to.shared.u64 t, %1; cvt.u32.u64 %0, t; }"
        : "=r"(a) : "l"(p));
    return a;
}
__device__ __forceinline__ void cp_async16(uint32_t dst, const void* src) {
    asm volatile("cp.async.cg.shared.global [%0], [%1], 16;"
                 :: "r"(dst), "l"(src) : "memory");
}
#define CP_COMMIT() asm volatile("cp.async.commit_group;" ::: "memory")
#define CP_WAIT1()  asm volatile("cp.async.wait_group 1;" ::: "memory")
#define CP_WAIT0()  asm volatile("cp.async.wait_group 0;" ::: "memory")

__device__ __forceinline__ void ldm_x4(uint32_t& r0, uint32_t& r1,
                                       uint32_t& r2, uint32_t& r3, uint32_t a) {
    asm volatile("ldmatrix.sync.aligned.m8n8.x4.shared.b16 {%0,%1,%2,%3}, [%4];"
                 : "=r"(r0), "=r"(r1), "=r"(r2), "=r"(r3) : "r"(a));
}
__device__ __forceinline__ void ldm_x4_t(uint32_t& r0, uint32_t& r1,
                                         uint32_t& r2, uint32_t& r3, uint32_t a) {
    asm volatile("ldmatrix.sync.aligned.m8n8.x4.trans.shared.b16 {%0,%1,%2,%3}, [%4];"
                 : "=r"(r0), "=r"(r1), "=r"(r2), "=r"(r3) : "r"(a));
}
__device__ __forceinline__ void mma16816(float* d, const uint32_t* a,
                                         uint32_t b0, uint32_t b1) {
    asm volatile(
        "mma.sync.aligned.m16n8k16.row.col.f32.f16.f16.f32 "
        "{%0,%1,%2,%3}, {%4,%5,%6,%7}, {%8,%9}, {%0,%1,%2,%3};"
        : "+f"(d[0]), "+f"(d[1]), "+f"(d[2]), "+f"(d[3])
        : "r"(a[0]), "r"(a[1]), "r"(a[2]), "r"(a[3]), "r"(b0), "r"(b1));
}
__device__ __forceinline__ uint32_t pack_h2(float lo, float hi) {
    uint32_t r;
    asm("cvt.rn.f16x2.f32 %0, %1, %2;" : "=r"(r) : "f"(hi), "f"(lo));
    return r;
}

// ---------------- conversion kernel ----------------
__global__ void cvt_h(const float* __restrict__ s, __half* __restrict__ d, int n4)
{
    int i = blockIdx.x * blockDim.x + threadIdx.x;
    if (i >= n4) return;
    float4 v = *(const float4*)(s + (size_t)i * 4);
    *(__half2*)(d + (size_t)i * 4)     = __halves2half2(__float2half_rn(v.x), __float2half_rn(v.y));
    *(__half2*)(d + (size_t)i * 4 + 2) = __halves2half2(__float2half_rn(v.z), __float2half_rn(v.w));
}

// ---------------- mma.sync GEMM + fused epilogues ----------------
// C = A*B^T. npass=2: accumulate Ahi then Alo; npass=1: Ahi only.
// mode 0: fp32 out to Cf.
// mode 1 (q+lat): col<2048 -> rope -> O1h; col>=2048 -> split -> (O2h,O2l)
// mode 2 (k+v):   col<128  -> rope -> O1h; col>=128  -> cvt -> O2h
#define GBK 32
#define GSTG 3
#define GTB 8192
#define GM_SMEM (2 * GSTG * GTB)

__global__ __launch_bounds__(256, 2) void gemm_f16x2(
    const __half* __restrict__ Ahi, const __half* __restrict__ Alo,
    const __half* __restrict__ Bh, float* __restrict__ Cf,
    __half* __restrict__ O1h,
    __half* __restrict__ O2h, __half* __restrict__ O2l,
    const float* __restrict__ cs, const float* __restrict__ sn,
    int N, int K, int mode, int npass)
{
    extern __shared__ char smraw[];
    const uint32_t sA = smem_u32(smraw);
    const uint32_t sB = sA + GSTG * GTB;

    const int tid  = threadIdx.x;
    const int wid  = tid >> 5;
    const int lane = tid & 31;
    const int wm = wid >> 2;
    const int wn = wid & 3;
    const int n0 = blockIdx.x * 128;
    const int m0 = blockIdx.y * 128;

    const int KB = K / GBK;
    const int total = npass * KB;

    float acc[4][4][4];
#pragma unroll
    for (int i = 0; i < 4; i++)
#pragma unroll
        for (int j = 0; j < 4; j++)
#pragma unroll
            for (int u = 0; u < 4; u++) acc[i][j][u] = 0.f;

    auto load_stage = [&](int j, int s) {
        const int kc = (j >= KB) ? (j - KB) : j;
        const __half* A = (j >= KB) ? Alo : Ahi;
        const uint32_t as = sA + (uint32_t)s * GTB;
        const uint32_t bs = sB + (uint32_t)s * GTB;
#pragma unroll
        for (int i = 0; i < 2; i++) {
            int ch  = tid + i * 256;
            int row = ch >> 2;
            int c   = ch & 3;
            int csw = c ^ ((row >> 1) & 3);
            uint32_t off = (uint32_t)(row * 64 + csw * 16);
            cp_async16(as + off, A  + (size_t)(m0 + row) * K + kc * GBK + c * 8);
            cp_async16(bs + off, Bh + (size_t)(n0 + row) * K + kc * GBK + c * 8);
        }
    };

    load_stage(0, 0); CP_COMMIT();
    load_stage(1, 1); CP_COMMIT();

    for (int j = 0; j < total; j++) {
        const int s = j % GSTG;
        CP_WAIT1();
        __syncthreads();
        if (j + 2 < total) load_stage(j + 2, (j + 2) % GSTG);
        CP_COMMIT();

        const uint32_t as = sA + (uint32_t)s * GTB;
        const uint32_t bs = sB + (uint32_t)s * GTB;
#pragma unroll
        for (int kk = 0; kk < 2; kk++) {
            uint32_t a[4][4], b[2][4];
#pragma unroll
            for (int mt = 0; mt < 4; mt++) {
                int row = wm * 64 + mt * 16 + (lane & 15);
                int cc  = kk * 2 + (lane >> 4);
                int csw = cc ^ ((row >> 1) & 3);
                ldm_x4(a[mt][0], a[mt][1], a[mt][2], a[mt][3],
                       as + (uint32_t)(row * 64 + csw * 16));
            }
#pragma unroll
            for (int np = 0; np < 2; np++) {
                int row = wn * 32 + np * 16 + (lane & 15);
                int cc  = kk * 2 + (lane >> 4);
                int csw = cc ^ ((row >> 1) & 3);
                ldm_x4(b[np][0], b[np][1], b[np][2], b[np][3],
                       bs + (uint32_t)(row * 64 + csw * 16));
            }
#pragma unroll
            for (int mt = 0; mt < 4; mt++)
#pragma unroll
                for (int nt = 0; nt < 4; nt++)
                    mma16816(acc[mt][nt], a[mt],
                             b[nt >> 1][nt & 1], b[nt >> 1][(nt & 1) + 2]);
        }
        __syncthreads();
    }

    // ---- fused epilogue ----
    const int r0g = m0 + wm * 64 + (lane >> 2);
    const int c0g = n0 + wn * 32 + (lane & 3) * 2;
#pragma unroll
    for (int mt = 0; mt < 4; mt++)
#pragma unroll
        for (int nt = 0; nt < 4; nt++)
#pragma unroll
            for (int u = 0; u < 2; u++) {
                const int rg = r0g + mt * 16 + u * 8;
                const int cg = c0g + nt * 8;
                float v0 = acc[mt][nt][u * 2];
                float v1 = acc[mt][nt][u * 2 + 1];
                if (mode == 0) {
                    *(float2*)(Cf + (size_t)rg * N + cg) = make_float2(v0, v1);
                } else if (mode == 1) {
                    const int t = rg & (T_ - 1);
                    if (cg < C_) {
                        int jj = (cg & 127) >> 1;
                        float c = cs[t * 64 + jj], s = sn[t * 64 + jj];
                        float o0 = v0 * c - v1 * s;
                        float o1 = v0 * s + v1 * c;
                        *(__half2*)(O1h + (size_t)rg * C_ + cg) =
                            __halves2half2(__float2half_rn(o0), __float2half_rn(o1));
                    } else {
                        __half h0 = __float2half_rn(v0), h1 = __float2half_rn(v1);
                        size_t o = (size_t)rg * L_ + (cg - C_);
                        *(__half2*)(O2h + o) = __halves2half2(h0, h1);
                        *(__half2*)(O2l + o) = __halves2half2(
                            __float2half_rn(v0 - __half2float(h0)),
                            __float2half_rn(v1 - __half2float(h1)));
                    }
                } else {
                    const int t = rg & (T_ - 1);
                    if (cg < D_) {
                        int jj = cg >> 1;
                        float c = cs[t * 64 + jj], s = sn[t * 64 + jj];
                        float o0 = v0 * c - v1 * s;
                        float o1 = v0 * s + v1 * c;
                        *(__half2*)(O1h + (size_t)rg * D_ + cg) =
                            __halves2half2(__float2half_rn(o0), __float2half_rn(o1));
                    } else {
                        *(__half2*)(O2h + (size_t)rg * D_ + (cg - D_)) =
                            __halves2half2(__float2half_rn(v0), __float2half_rn(v1));
                    }
                }
            }
}

// ---------------- mma.sync flash attention (fp16, single-pass QK and PV) ----------------
#define AST 136
#define QT_B (128 * AST * 2)
#define KT_B (64 * AST * 2)
#define STG_B (2 * KT_B)
#define ATT_SMEM (QT_B + 2 * STG_B)   // 104448

__global__ __launch_bounds__(256, 1) void attn_mma(
    const __half* __restrict__ qh, const __half* __restrict__ kh,
    const __half* __restrict__ vh, __half* __restrict__ yh)
{
    extern __shared__ char smraw[];
    const uint32_t sQ   = smem_u32(smraw);
    const uint32_t sStg = sQ + QT_B;

    const int tid  = threadIdx.x;
    const int wid  = tid >> 5;
    const int lane = tid & 31;
    const int qt = (T_ / 128 - 1) - blockIdx.x;
    const int h  = blockIdx.y, b = blockIdx.z;
    const int t0 = qt * 128;
    const int jmax = 2 * qt + 1;
    const float scale = 0.08838834764831845f;

    {
        const size_t qb = (((size_t)b * T_ + t0) * H_ + h) * D_;
#pragma unroll
        for (int i = 0; i < 8; i++) {
            int ch  = tid + i * 256;
            int row = ch >> 4;
            int c16 = ch & 15;
            uint32_t doff = (uint32_t)(row * AST + c16 * 8) * 2;
            cp_async16(sQ + doff, qh + qb + (size_t)row * (H_ * D_) + c16 * 8);
        }
    }
    auto load_stage = [&](int j, int s) {
        const uint32_t sb = sStg + (uint32_t)s * STG_B;
        const size_t   gb = ((size_t)b * T_ + j * 64) * D_;
#pragma unroll
        for (int i = 0; i < 4; i++) {
            int ch  = tid + i * 256;
            int row = ch >> 4;
            int c16 = ch & 15;
            uint32_t doff = (uint32_t)(row * AST + c16 * 8) * 2;
            size_t   soff = gb + (size_t)row * D_ + c16 * 8;
            cp_async16(sb + doff,        kh + soff);
            cp_async16(sb + KT_B + doff, vh + soff);
        }
    };
    load_stage(0, 0); CP_COMMIT();
    load_stage(1, 1); CP_COMMIT();

    float m0 = -3.0e38f, m1 = -3.0e38f, l0 = 0.f, l1 = 0.f;
    float yacc[16][4];
#pragma unroll
    for (int nt = 0; nt < 16; nt++)
#pragma unroll
        for (int u = 0; u < 4; u++) yacc[nt][u] = 0.f;

    const int rloc = wid * 16 + (lane >> 2);

    for (int j = 0; j <= jmax; j++) {
        const int s = j & 1;
        if (j < jmax) { CP_WAIT1(); } else { CP_WAIT0(); }
        __syncthreads();
        const uint32_t sKh = sStg + (uint32_t)s * STG_B;
        const uint32_t sVh = sKh + KT_B;

        float sacc[8][4];
#pragma unroll
        for (int nt = 0; nt < 8; nt++)
#pragma unroll
            for (int u = 0; u < 4; u++) sacc[nt][u] = 0.f;

#pragma unroll
        for (int kk = 0; kk < 8; kk++) {
            uint32_t a[4], bb[4][4];
            {
                int row = wid * 16 + (lane & 15);
                int col = kk * 16 + (lane >> 4) * 8;
                ldm_x4(a[0], a[1], a[2], a[3],
                       sQ + (uint32_t)(row * AST + col) * 2);
            }
#pragma unroll
            for (int nt2 = 0; nt2 < 4; nt2++) {
                int row = nt2 * 16 + (lane & 15);
                int col = kk * 16 + (lane >> 4) * 8;
                ldm_x4(bb[nt2][0], bb[nt2][1], bb[nt2][2], bb[nt2][3],
                       sKh + (uint32_t)(row * AST + col) * 2);
            }
#pragma unroll
            for (int nt = 0; nt < 8; nt++)
                mma16816(sacc[nt], a,
                         bb[nt >> 1][nt & 1], bb[nt >> 1][(nt & 1) + 2]);
        }

        const bool need_mask = (j >= jmax - 1);
#pragma unroll
        for (int nt = 0; nt < 8; nt++)
#pragma unroll
            for (int u = 0; u < 4; u++) {
                float v = sacc[nt][u] * scale;
                if (need_mask) {
                    int rg = t0 + rloc + (u >> 1) * 8;
                    int cg = j * 64 + nt * 8 + (lane & 3) * 2 + (u & 1);
                    if (cg > rg) v = -1.0e30f;
                }
                sacc[nt][u] = v;
            }

        float rx0 = -3.0e38f, rx1 = -3.0e38f;
#pragma unroll
        for (int nt = 0; nt < 8; nt++) {
            rx0 = fmaxf(rx0, fmaxf(sacc[nt][0], sacc[nt][1]));
            rx1 = fmaxf(rx1, fmaxf(sacc[nt][2], sacc[nt][3]));
        }
        rx0 = fmaxf(rx0, __shfl_xor_sync(0xffffffffu, rx0, 1));
        rx0 = fmaxf(rx0, __shfl_xor_sync(0xffffffffu, rx0, 2));
        rx1 = fmaxf(rx1, __shfl_xor_sync(0xffffffffu, rx1, 1));
        rx1 = fmaxf(rx1, __shfl_xor_sync(0xffffffffu, rx1, 2));
        float mn0 = fmaxf(m0, rx0), mn1 = fmaxf(m1, rx1);
        float sc0 = __expf(m0 - mn0), sc1 = __expf(m1 - mn1);
        m0 = mn0; m1 = mn1;

        float rs0 = 0.f, rs1 = 0.f;
#pragma unroll
        for (int nt = 0; nt < 8; nt++) {
            sacc[nt][0] = __expf(sacc[nt][0] - mn0);
            sacc[nt][1] = __expf(sacc[nt][1] - mn0);
            sacc[nt][2] = __expf(sacc[nt][2] - mn1);
            sacc[nt][3] = __expf(sacc[nt][3] - mn1);
            rs0 += sacc[nt][0] + sacc[nt][1];
            rs1 += sacc[nt][2] + sacc[nt][3];
        }
        rs0 += __shfl_xor_sync(0xffffffffu, rs0, 1);
        rs0 += __shfl_xor_sync(0xffffffffu, rs0, 2);
        rs1 += __shfl_xor_sync(0xffffffffu, rs1, 1);
        rs1 += __shfl_xor_sync(0xffffffffu, rs1, 2);
        l0 = l0 * sc0 + rs0;
        l1 = l1 * sc1 + rs1;

#pragma unroll
        for (int nt = 0; nt < 16; nt++) {
            yacc[nt][0] *= sc0; yacc[nt][1] *= sc0;
            yacc[nt][2] *= sc1; yacc[nt][3] *= sc1;
        }

        uint32_t pA[4][4];
#pragma unroll
        for (int kk2 = 0; kk2 < 4; kk2++) {
            const float* s0 = sacc[2 * kk2];
            const float* s1 = sacc[2 * kk2 + 1];
            pA[kk2][0] = pack_h2(s0[0], s0[1]);
            pA[kk2][1] = pack_h2(s0[2], s0[3]);
            pA[kk2][2] = pack_h2(s1[0], s1[1]);
            pA[kk2][3] = pack_h2(s1[2], s1[3]);
        }

#pragma unroll
        for (int kk2 = 0; kk2 < 4; kk2++) {
            uint32_t vb[8][4];
#pragma unroll
            for (int nt2 = 0; nt2 < 8; nt2++) {
                int row = kk2 * 16 + (lane & 15);
                int col = nt2 * 16 + (lane >> 4) * 8;
                ldm_x4_t(vb[nt2][0], vb[nt2][1], vb[nt2][2], vb[nt2][3],
                         sVh + (uint32_t)(row * AST + col) * 2);
            }
#pragma unroll
            for (int nt = 0; nt < 16; nt++)
                mma16816(yacc[nt], pA[kk2],
                         vb[nt >> 1][(nt & 1) * 2], vb[nt >> 1][(nt & 1) * 2 + 1]);
        }

        __syncthreads();
        if (j + 2 <= jmax) { load_stage(j + 2, s); CP_COMMIT(); }
    }

    const float inv0 = 1.f / l0, inv1 = 1.f / l1;
#pragma unroll
    for (int half = 0; half < 2; half++) {
        const int rg = t0 + rloc + half * 8;
        const float inv = half ? inv1 : inv0;
        __half* py = yh + (((size_t)b * T_ + rg) * H_ + h) * D_;
#pragma unroll
        for (int nt = 0; nt < 16; nt++) {
            int cg = nt * 8 + (lane & 3) * 2;
            *(__half2*)(py + cg) = __halves2half2(
                __float2half_rn(yacc[nt][half * 2]     * inv),
                __float2half_rn(yacc[nt][half * 2 + 1] * inv));
        }
    }
}

// ---------------- host launcher ----------------
extern "C" void kernel_launch(void* const* d_in, const int* in_sizes, int n_in,
                              void* d_out, int out_size)
{
    const float* x     = (const float*)d_in[0];
    const float* fcos  = (const float*)d_in[1];
    const float* fsin  = (const float*)d_in[2];
    const float* wq    = (const float*)d_in[3];
    const float* wkv   = (const float*)d_in[4];
    const float* wk_up = (const float*)d_in[5];
    const float* wv_up = (const float*)d_in[6];
    const float* wo    = (const float*)d_in[7];
    float* out = (float*)d_out;

    __half *xh, *qh, *lhi, *llo, *kh, *vh, *wqkvh, *wuph, *woh;
    cudaGetSymbolAddress((void**)&xh,    g_xh);
    cudaGetSymbolAddress((void**)&qh,    g_qh);
    cudaGetSymbolAddress((void**)&lhi,   g_lhi);
    cudaGetSymbolAddress((void**)&llo,   g_llo);
    cudaGetSymbolAddress((void**)&kh,    g_kh);
    cudaGetSymbolAddress((void**)&vh,    g_vh);
    cudaGetSymbolAddress((void**)&wqkvh, g_wqkvh);
    cudaGetSymbolAddress((void**)&wuph,  g_wuph);
    cudaGetSymbolAddress((void**)&woh,   g_woh);

    cudaFuncSetAttribute(gemm_f16x2,
                         cudaFuncAttributeMaxDynamicSharedMemorySize, GM_SMEM);
    cudaFuncSetAttribute(attn_mma,
                         cudaFuncAttributeMaxDynamicSharedMemorySize, ATT_SMEM);

    // conversions (all single fp16 now except lat which splits in-GEMM)
    cvt_h<<<(BT_*C_/4)/256, 256>>>(x, xh, BT_*C_/4);
    cvt_h<<<(H_*D_*C_/4)/256, 256>>>(wq, wqkvh, H_*D_*C_/4);
    cvt_h<<<(L_*C_/4)/256, 256>>>(wkv, wqkvh + (size_t)H_*D_*C_, L_*C_/4);
    cvt_h<<<(D_*L_/4)/256, 256>>>(wk_up, wuph, D_*L_/4);
    cvt_h<<<(D_*L_/4)/256, 256>>>(wv_up, wuph + (size_t)D_*L_, D_*L_/4);
    cvt_h<<<(C_*H_*D_/4)/256, 256>>>(wo, woh, C_*H_*D_/4);

    // q+lat projection (single-pass, x fp16): q -> rope fp16, lat -> hi/lo split
    gemm_f16x2<<<dim3(NQL/128, BT_/128), 256, GM_SMEM>>>(
        xh, xh, wqkvh, nullptr, qh, lhi, llo, fcos, fsin, NQL, C_, 1, 1);
    // k+v up-projection (2-pass lat split): k -> rope fp16, v -> fp16
    gemm_f16x2<<<dim3(NKV/128, BT_/128), 256, GM_SMEM>>>(
        lhi, llo, wuph, nullptr, kh, vh, nullptr, fcos, fsin, NKV, L_, 2, 2);

    // attention (single-pass): y fp16 overwrites xh (dead after q+lat GEMM)
    attn_mma<<<dim3(T_/128, H_, B_), 256, ATT_SMEM>>>(qh, kh, vh, xh);

    // output projection (single-pass), fp32 epilogue
    gemm_f16x2<<<dim3(C_/128, BT_/128), 256, GM_SMEM>>>(
        xh, xh, woh, out, nullptr, nullptr, nullptr,
        nullptr, nullptr, C_, H_*D_, 0, 1);
}

// round 17
// speedup vs baseline: 2.9814x; 1.0188x over previous
#include <cuda_runtime.h>
#include <cuda_fp16.h>
#include <math.h>
#include <stdint.h>

#define B_ 4
#define T_ 2048
#define C_ 2048
#define H_ 16
#define D_ 128
#define L_ 512
#define BT_ (B_*T_)
#define NQL 2560
#define NKV 256

// ---------------- scratch ----------------
__device__ __half g_xh[(size_t)BT_ * C_];       // x fp16 -> (after attn) y fp16
__device__ __half g_qh[(size_t)BT_ * C_];       // rope(q) fp16
__device__ __half g_lhi[(size_t)BT_ * L_];
__device__ __half g_llo[(size_t)BT_ * L_];
__device__ __half g_kh[(size_t)BT_ * D_];
__device__ __half g_vh[(size_t)BT_ * D_];
__device__ __half g_wqkvh[(size_t)NQL * C_];
__device__ __half g_wuph[(size_t)NKV * L_];
__device__ __half g_woh[(size_t)C_ * H_ * D_];

// ---------------- helpers ----------------
__device__ __forceinline__ uint32_t smem_u32(const void* p) {
    uint32_t a;
    asm("{ .reg .u64 t; cvta.to.shared.u64 t, %1; cvt.u32.u64 %0, t; }"
        : "=r"(a) : "l"(p));
    return a;
}
__device__ __forceinline__ void cp_async16(uint32_t dst, const void* src) {
    asm volatile("cp.async.cg.shared.global [%0], [%1], 16;"
                 :: "r"(dst), "l"(src) : "memory");
}
#define CP_COMMIT() asm volatile("cp.async.commit_group;" ::: "memory")
#define CP_WAIT1()  asm volatile("cp.async.wait_group 1;" ::: "memory")
#define CP_WAIT0()  asm volatile("cp.async.wait_group 0;" ::: "memory")

__device__ __forceinline__ void ldm_x4(uint32_t& r0, uint32_t& r1,
                                       uint32_t& r2, uint32_t& r3, uint32_t a) {
    asm volatile("ldmatrix.sync.aligned.m8n8.x4.shared.b16 {%0,%1,%2,%3}, [%4];"
                 : "=r"(r0), "=r"(r1), "=r"(r2), "=r"(r3) : "r"(a));
}
__device__ __forceinline__ void ldm_x4_t(uint32_t& r0, uint32_t& r1,
                                         uint32_t& r2, uint32_t& r3, uint32_t a) {
    asm volatile("ldmatrix.sync.aligned.m8n8.x4.trans.shared.b16 {%0,%1,%2,%3}, [%4];"
                 : "=r"(r0), "=r"(r1), "=r"(r2), "=r"(r3) : "r"(a));
}
__device__ __forceinline__ void mma16816(float* d, const uint32_t* a,
                                         uint32_t b0, uint32_t b1) {
    asm volatile(
        "mma.sync.aligned.m16n8k16.row.col.f32.f16.f16.f32 "
        "{%0,%1,%2,%3}, {%4,%5,%6,%7}, {%8,%9}, {%0,%1,%2,%3};"
        : "+f"(d[0]), "+f"(d[1]), "+f"(d[2]), "+f"(d[3])
        : "r"(a[0]), "r"(a[1]), "r"(a[2]), "r"(a[3]), "r"(b0), "r"(b1));
}
__device__ __forceinline__ uint32_t pack_h2(float lo, float hi) {
    uint32_t r;
    asm("cvt.rn.f16x2.f32 %0, %1, %2;" : "=r"(r) : "f"(hi), "f"(lo));
    return r;
}

// ---------------- conversion kernel ----------------
__global__ void cvt_h(const float* __restrict__ s, __half* __restrict__ d, int n4)
{
    int i = blockIdx.x * blockDim.x + threadIdx.x;
    if (i >= n4) return;
    float4 v = *(const float4*)(s + (size_t)i * 4);
    *(__half2*)(d + (size_t)i * 4)     = __halves2half2(__float2half_rn(v.x), __float2half_rn(v.y));
    *(__half2*)(d + (size_t)i * 4 + 2) = __halves2half2(__float2half_rn(v.z), __float2half_rn(v.w));
}

// ---------------- mma.sync GEMM + fused epilogues ----------------
#define GBK 32
#define GSTG 3
#define GTB 8192
#define GM_SMEM (2 * GSTG * GTB)

__global__ __launch_bounds__(256, 2) void gemm_f16x2(
    const __half* __restrict__ Ahi, const __half* __restrict__ Alo,
    const __half* __restrict__ Bh, float* __restrict__ Cf,
    __half* __restrict__ O1h,
    __half* __restrict__ O2h, __half* __restrict__ O2l,
    const float* __restrict__ cs, const float* __restrict__ sn,
    int N, int K, int mode, int npass)
{
    extern __shared__ char smraw[];
    const uint32_t sA = smem_u32(smraw);
    const uint32_t sB = sA + GSTG * GTB;

    const int tid  = threadIdx.x;
    const int wid  = tid >> 5;
    const int lane = tid & 31;
    const int wm = wid >> 2;
    const int wn = wid & 3;
    const int n0 = blockIdx.x * 128;
    const int m0 = blockIdx.y * 128;

    const int KB = K / GBK;
    const int total = npass * KB;

    float acc[4][4][4];
#pragma unroll
    for (int i = 0; i < 4; i++)
#pragma unroll
        for (int j = 0; j < 4; j++)
#pragma unroll
            for (int u = 0; u < 4; u++) acc[i][j][u] = 0.f;

    auto load_stage = [&](int j, int s) {
        const int kc = (j >= KB) ? (j - KB) : j;
        const __half* A = (j >= KB) ? Alo : Ahi;
        const uint32_t as = sA + (uint32_t)s * GTB;
        const uint32_t bs = sB + (uint32_t)s * GTB;
#pragma unroll
        for (int i = 0; i < 2; i++) {
            int ch  = tid + i * 256;
            int row = ch >> 2;
            int c   = ch & 3;
            int csw = c ^ ((row >> 1) & 3);
            uint32_t off = (uint32_t)(row * 64 + csw * 16);
            cp_async16(as + off, A  + (size_t)(m0 + row) * K + kc * GBK + c * 8);
            cp_async16(bs + off, Bh + (size_t)(n0 + row) * K + kc * GBK + c * 8);
        }
    };

    load_stage(0, 0); CP_COMMIT();
    load_stage(1, 1); CP_COMMIT();

    for (int j = 0; j < total; j++) {
        const int s = j % GSTG;
        CP_WAIT1();
        __syncthreads();
        if (j + 2 < total) load_stage(j + 2, (j + 2) % GSTG);
        CP_COMMIT();

        const uint32_t as = sA + (uint32_t)s * GTB;
        const uint32_t bs = sB + (uint32_t)s * GTB;
#pragma unroll
        for (int kk = 0; kk < 2; kk++) {
            uint32_t a[4][4], b[2][4];
#pragma unroll
            for (int mt = 0; mt < 4; mt++) {
                int row = wm * 64 + mt * 16 + (lane & 15);
                int cc  = kk * 2 + (lane >> 4);
                int csw = cc ^ ((row >> 1) & 3);
                ldm_x4(a[mt][0], a[mt][1], a[mt][2], a[mt][3],
                       as + (uint32_t)(row * 64 + csw * 16));
            }
#pragma unroll
            for (int np = 0; np < 2; np++) {
                int row = wn * 32 + np * 16 + (lane & 15);
                int cc  = kk * 2 + (lane >> 4);
                int csw = cc ^ ((row >> 1) & 3);
                ldm_x4(b[np][0], b[np][1], b[np][2], b[np][3],
                       bs + (uint32_t)(row * 64 + csw * 16));
            }
#pragma unroll
            for (int mt = 0; mt < 4; mt++)
#pragma unroll
                for (int nt = 0; nt < 4; nt++)
                    mma16816(acc[mt][nt], a[mt],
                             b[nt >> 1][nt & 1], b[nt >> 1][(nt & 1) + 2]);
        }
        // NOTE: no end-of-loop barrier needed — next iter's top barrier
        // (after CP_WAIT) orders all reads of stage (j+2)%3 before its reuse.
    }

    // ---- fused epilogue ----
    const int r0g = m0 + wm * 64 + (lane >> 2);
    const int c0g = n0 + wn * 32 + (lane & 3) * 2;
#pragma unroll
    for (int mt = 0; mt < 4; mt++)
#pragma unroll
        for (int nt = 0; nt < 4; nt++)
#pragma unroll
            for (int u = 0; u < 2; u++) {
                const int rg = r0g + mt * 16 + u * 8;
                const int cg = c0g + nt * 8;
                float v0 = acc[mt][nt][u * 2];
                float v1 = acc[mt][nt][u * 2 + 1];
                if (mode == 0) {
                    *(float2*)(Cf + (size_t)rg * N + cg) = make_float2(v0, v1);
                } else if (mode == 1) {
                    const int t = rg & (T_ - 1);
                    if (cg < C_) {
                        int jj = (cg & 127) >> 1;
                        float c = cs[t * 64 + jj], s = sn[t * 64 + jj];
                        float o0 = v0 * c - v1 * s;
                        float o1 = v0 * s + v1 * c;
                        *(__half2*)(O1h + (size_t)rg * C_ + cg) =
                            __halves2half2(__float2half_rn(o0), __float2half_rn(o1));
                    } else {
                        __half h0 = __float2half_rn(v0), h1 = __float2half_rn(v1);
                        size_t o = (size_t)rg * L_ + (cg - C_);
                        *(__half2*)(O2h + o) = __halves2half2(h0, h1);
                        *(__half2*)(O2l + o) = __halves2half2(
                            __float2half_rn(v0 - __half2float(h0)),
                            __float2half_rn(v1 - __half2float(h1)));
                    }
                } else {
                    const int t = rg & (T_ - 1);
                    if (cg < D_) {
                        int jj = cg >> 1;
                        float c = cs[t * 64 + jj], s = sn[t * 64 + jj];
                        float o0 = v0 * c - v1 * s;
                        float o1 = v0 * s + v1 * c;
                        *(__half2*)(O1h + (size_t)rg * D_ + cg) =
                            __halves2half2(__float2half_rn(o0), __float2half_rn(o1));
                    } else {
                        *(__half2*)(O2h + (size_t)rg * D_ + (cg - D_)) =
                            __halves2half2(__float2half_rn(v0), __float2half_rn(v1));
                    }
                }
            }
}

// ---------------- mma.sync flash attention (fp16, BR=128, BC=128) ----------------
#define AST 136
#define QT_B (128 * AST * 2)          // 34816 B
#define KT_B (128 * AST * 2)          // 34816 B (now 128 kv rows)
#define STG_B (2 * KT_B)              // kh + vh = 69632
#define ATT_SMEM (QT_B + 2 * STG_B)   // 174080

__global__ __launch_bounds__(256, 1) void attn_mma(
    const __half* __restrict__ qh, const __half* __restrict__ kh,
    const __half* __restrict__ vh, __half* __restrict__ yh)
{
    extern __shared__ char smraw[];
    const uint32_t sQ   = smem_u32(smraw);
    const uint32_t sStg = sQ + QT_B;

    const int tid  = threadIdx.x;
    const int wid  = tid >> 5;
    const int lane = tid & 31;
    const int qt = (T_ / 128 - 1) - blockIdx.x;   // longest work first
    const int h  = blockIdx.y, b = blockIdx.z;
    const int t0 = qt * 128;
    const int jmax = qt;                           // 128-col kv tiles
    const float scale = 0.08838834764831845f;

    {
        const size_t qb = (((size_t)b * T_ + t0) * H_ + h) * D_;
#pragma unroll
        for (int i = 0; i < 8; i++) {
            int ch  = tid + i * 256;
            int row = ch >> 4;
            int c16 = ch & 15;
            uint32_t doff = (uint32_t)(row * AST + c16 * 8) * 2;
            cp_async16(sQ + doff, qh + qb + (size_t)row * (H_ * D_) + c16 * 8);
        }
    }
    auto load_stage = [&](int j, int s) {
        const uint32_t sb = sStg + (uint32_t)s * STG_B;
        const size_t   gb = ((size_t)b * T_ + j * 128) * D_;
#pragma unroll
        for (int i = 0; i < 8; i++) {
            int ch  = tid + i * 256;              // 2048 chunks per tensor
            int row = ch >> 4;
            int c16 = ch & 15;
            uint32_t doff = (uint32_t)(row * AST + c16 * 8) * 2;
            size_t   soff = gb + (size_t)row * D_ + c16 * 8;
            cp_async16(sb + doff,        kh + soff);
            cp_async16(sb + KT_B + doff, vh + soff);
        }
    };
    load_stage(0, 0); CP_COMMIT();
    if (jmax >= 1) { load_stage(1, 1); CP_COMMIT(); }

    float m0 = -3.0e38f, m1 = -3.0e38f, l0 = 0.f, l1 = 0.f;
    float yacc[16][4];
#pragma unroll
    for (int nt = 0; nt < 16; nt++)
#pragma unroll
        for (int u = 0; u < 4; u++) yacc[nt][u] = 0.f;

    const int rloc = wid * 16 + (lane >> 2);

    for (int j = 0; j <= jmax; j++) {
        const int s = j & 1;
        if (j < jmax) { CP_WAIT1(); } else { CP_WAIT0(); }
        __syncthreads();
        const uint32_t sKh = sStg + (uint32_t)s * STG_B;
        const uint32_t sVh = sKh + KT_B;

        // ---- S = Q K^T over 128 kv cols (16 n-tiles) ----
        float sacc[16][4];
#pragma unroll
        for (int nt = 0; nt < 16; nt++)
#pragma unroll
            for (int u = 0; u < 4; u++) sacc[nt][u] = 0.f;

#pragma unroll
        for (int kk = 0; kk < 8; kk++) {
            uint32_t a[4], bb[8][4];
            {
                int row = wid * 16 + (lane & 15);
                int col = kk * 16 + (lane >> 4) * 8;
                ldm_x4(a[0], a[1], a[2], a[3],
                       sQ + (uint32_t)(row * AST + col) * 2);
            }
#pragma unroll
            for (int nt2 = 0; nt2 < 8; nt2++) {
                int row = nt2 * 16 + (lane & 15);
                int col = kk * 16 + (lane >> 4) * 8;
                ldm_x4(bb[nt2][0], bb[nt2][1], bb[nt2][2], bb[nt2][3],
                       sKh + (uint32_t)(row * AST + col) * 2);
            }
#pragma unroll
            for (int nt = 0; nt < 16; nt++)
                mma16816(sacc[nt], a,
                         bb[nt >> 1][nt & 1], bb[nt >> 1][(nt & 1) + 2]);
        }

        // ---- scale + causal mask (diagonal tile only) ----
        const bool need_mask = (j == jmax);
#pragma unroll
        for (int nt = 0; nt < 16; nt++)
#pragma unroll
            for (int u = 0; u < 4; u++) {
                float v = sacc[nt][u] * scale;
                if (need_mask) {
                    int rl = rloc + (u >> 1) * 8;
                    int cl = nt * 8 + (lane & 3) * 2 + (u & 1);
                    if (cl > rl) v = -1.0e30f;
                }
                sacc[nt][u] = v;
            }

        // ---- online softmax ----
        float rx0 = -3.0e38f, rx1 = -3.0e38f;
#pragma unroll
        for (int nt = 0; nt < 16; nt++) {
            rx0 = fmaxf(rx0, fmaxf(sacc[nt][0], sacc[nt][1]));
            rx1 = fmaxf(rx1, fmaxf(sacc[nt][2], sacc[nt][3]));
        }
        rx0 = fmaxf(rx0, __shfl_xor_sync(0xffffffffu, rx0, 1));
        rx0 = fmaxf(rx0, __shfl_xor_sync(0xffffffffu, rx0, 2));
        rx1 = fmaxf(rx1, __shfl_xor_sync(0xffffffffu, rx1, 1));
        rx1 = fmaxf(rx1, __shfl_xor_sync(0xffffffffu, rx1, 2));
        float mn0 = fmaxf(m0, rx0), mn1 = fmaxf(m1, rx1);
        float sc0 = __expf(m0 - mn0), sc1 = __expf(m1 - mn1);
        m0 = mn0; m1 = mn1;

        float rs0 = 0.f, rs1 = 0.f;
#pragma unroll
        for (int nt = 0; nt < 16; nt++) {
            sacc[nt][0] = __expf(sacc[nt][0] - mn0);
            sacc[nt][1] = __expf(sacc[nt][1] - mn0);
            sacc[nt][2] = __expf(sacc[nt][2] - mn1);
            sacc[nt][3] = __expf(sacc[nt][3] - mn1);
            rs0 += sacc[nt][0] + sacc[nt][1];
            rs1 += sacc[nt][2] + sacc[nt][3];
        }
        rs0 += __shfl_xor_sync(0xffffffffu, rs0, 1);
        rs0 += __shfl_xor_sync(0xffffffffu, rs0, 2);
        rs1 += __shfl_xor_sync(0xffffffffu, rs1, 1);
        rs1 += __shfl_xor_sync(0xffffffffu, rs1, 2);
        l0 = l0 * sc0 + rs0;
        l1 = l1 * sc1 + rs1;

#pragma unroll
        for (int nt = 0; nt < 16; nt++) {
            yacc[nt][0] *= sc0; yacc[nt][1] *= sc0;
            yacc[nt][2] *= sc1; yacc[nt][3] *= sc1;
        }

        // ---- P a-fragments (fp16), 8 k16 groups over 128 cols ----
        uint32_t pA[8][4];
#pragma unroll
        for (int kk2 = 0; kk2 < 8; kk2++) {
            const float* s0 = sacc[2 * kk2];
            const float* s1 = sacc[2 * kk2 + 1];
            pA[kk2][0] = pack_h2(s0[0], s0[1]);
            pA[kk2][1] = pack_h2(s0[2], s0[3]);
            pA[kk2][2] = pack_h2(s1[0], s1[1]);
            pA[kk2][3] = pack_h2(s1[2], s1[3]);
        }

        // ---- Y += P V ----
#pragma unroll
        for (int kk2 = 0; kk2 < 8; kk2++) {
            uint32_t vb[8][4];
#pragma unroll
            for (int nt2 = 0; nt2 < 8; nt2++) {
                int row = kk2 * 16 + (lane & 15);
                int col = nt2 * 16 + (lane >> 4) * 8;
                ldm_x4_t(vb[nt2][0], vb[nt2][1], vb[nt2][2], vb[nt2][3],
                         sVh + (uint32_t)(row * AST + col) * 2);
            }
#pragma unroll
            for (int nt = 0; nt < 16; nt++)
                mma16816(yacc[nt], pA[kk2],
                         vb[nt >> 1][(nt & 1) * 2], vb[nt >> 1][(nt & 1) * 2 + 1]);
        }

        __syncthreads();   // required: next load overwrites the just-read stage
        if (j + 2 <= jmax) { load_stage(j + 2, s); CP_COMMIT(); }
    }

    const float inv0 = 1.f / l0, inv1 = 1.f / l1;
#pragma unroll
    for (int half = 0; half < 2; half++) {
        const int rg = t0 + rloc + half * 8;
        const float inv = half ? inv1 : inv0;
        __half* py = yh + (((size_t)b * T_ + rg) * H_ + h) * D_;
#pragma unroll
        for (int nt = 0; nt < 16; nt++) {
            int cg = nt * 8 + (lane & 3) * 2;
            *(__half2*)(py + cg) = __halves2half2(
                __float2half_rn(yacc[nt][half * 2]     * inv),
                __float2half_rn(yacc[nt][half * 2 + 1] * inv));
        }
    }
}

// ---------------- host launcher ----------------
extern "C" void kernel_launch(void* const* d_in, const int* in_sizes, int n_in,
                              void* d_out, int out_size)
{
    const float* x     = (const float*)d_in[0];
    const float* fcos  = (const float*)d_in[1];
    const float* fsin  = (const float*)d_in[2];
    const float* wq    = (const float*)d_in[3];
    const float* wkv   = (const float*)d_in[4];
    const float* wk_up = (const float*)d_in[5];
    const float* wv_up = (const float*)d_in[6];
    const float* wo    = (const float*)d_in[7];
    float* out = (float*)d_out;

    __half *xh, *qh, *lhi, *llo, *kh, *vh, *wqkvh, *wuph, *woh;
    cudaGetSymbolAddress((void**)&xh,    g_xh);
    cudaGetSymbolAddress((void**)&qh,    g_qh);
    cudaGetSymbolAddress((void**)&lhi,   g_lhi);
    cudaGetSymbolAddress((void**)&llo,   g_llo);
    cudaGetSymbolAddress((void**)&kh,    g_kh);
    cudaGetSymbolAddress((void**)&vh,    g_vh);
    cudaGetSymbolAddress((void**)&wqkvh, g_wqkvh);
    cudaGetSymbolAddress((void**)&wuph,  g_wuph);
    cudaGetSymbolAddress((void**)&woh,   g_woh);

    cudaFuncSetAttribute(gemm_f16x2,
                         cudaFuncAttributeMaxDynamicSharedMemorySize, GM_SMEM);
    cudaFuncSetAttribute(attn_mma,
                         cudaFuncAttributeMaxDynamicSharedMemorySize, ATT_SMEM);

    // conversions
    cvt_h<<<(BT_*C_/4)/256, 256>>>(x, xh, BT_*C_/4);
    cvt_h<<<(H_*D_*C_/4)/256, 256>>>(wq, wqkvh, H_*D_*C_/4);
    cvt_h<<<(L_*C_/4)/256, 256>>>(wkv, wqkvh + (size_t)H_*D_*C_, L_*C_/4);
    cvt_h<<<(D_*L_/4)/256, 256>>>(wk_up, wuph, D_*L_/4);
    cvt_h<<<(D_*L_/4)/256, 256>>>(wv_up, wuph + (size_t)D_*L_, D_*L_/4);
    cvt_h<<<(C_*H_*D_/4)/256, 256>>>(wo, woh, C_*H_*D_/4);

    // q+lat projection (single-pass): q -> rope fp16, lat -> hi/lo split
    gemm_f16x2<<<dim3(NQL/128, BT_/128), 256, GM_SMEM>>>(
        xh, xh, wqkvh, nullptr, qh, lhi, llo, fcos, fsin, NQL, C_, 1, 1);
    // k+v up-projection (2-pass lat split): k -> rope fp16, v -> fp16
    gemm_f16x2<<<dim3(NKV/128, BT_/128), 256, GM_SMEM>>>(
        lhi, llo, wuph, nullptr, kh, vh, nullptr, fcos, fsin, NKV, L_, 2, 2);

    // attention (single-pass, BC=128): y fp16 overwrites xh
    attn_mma<<<dim3(T_/128, H_, B_), 256, ATT_SMEM>>>(qh, kh, vh, xh);

    // output projection (single-pass), fp32 epilogue
    gemm_f16x2<<<dim3(C_/128, BT_/128), 256, GM_SMEM>>>(
        xh, xh, woh, out, nullptr, nullptr, nullptr,
        nullptr, nullptr, C_, H_*D_, 0, 1);
}